// round 1
// baseline (speedup 1.0000x reference)
#include <cuda_runtime.h>
#include <math.h>

#define B_ 2
#define S_ 2048
#define E_ 1024
#define H_ 16
#define D_ 64
#define M_ (B_*S_)            // 4096 rows for projection GEMMs
#define SCALE_ 0.125f         // D^-0.5 = 64^-0.5

// Scratch (device globals: allocation-free per harness rules)
__device__ float g_q[B_*H_*S_*D_];   // [B,H,S,D]
__device__ float g_k[B_*H_*S_*D_];
__device__ float g_v[B_*H_*S_*D_];
__device__ float g_att[B_*S_*E_];    // [B,S,E] (heads merged)

// ---------------------------------------------------------------------------
// GEMM: C[m][n] = sum_k A[m][k] * W[n][k]    (A: MxK row-major, W: NxK row-major)
// M=4096, N=1024, K=1024.  BM=BN=64, BK=16, 256 threads, 4x4 per-thread tile.
// HEAD_LAYOUT: scatter output into [B,H,S,D]; else plain [M,N].
// ---------------------------------------------------------------------------
template<bool HEAD_LAYOUT>
__global__ __launch_bounds__(256)
void gemm_nt_kernel(const float* __restrict__ A, const float* __restrict__ W,
                    float* __restrict__ C)
{
    const int BM = 64, BN = 64, BK = 16;
    __shared__ float As[BK][BM + 1];
    __shared__ float Bs[BK][BN + 1];

    const int tid = threadIdx.x;
    const int tx = tid & 15;          // 0..15 -> n micro
    const int ty = tid >> 4;          // 0..15 -> m micro
    const int m0 = blockIdx.y * BM;
    const int n0 = blockIdx.x * BN;

    const int lrow = tid >> 2;        // 0..63
    const int lk   = (tid & 3) * 4;   // 0,4,8,12

    float acc[4][4];
    #pragma unroll
    for (int i = 0; i < 4; i++)
        #pragma unroll
        for (int j = 0; j < 4; j++) acc[i][j] = 0.0f;

    const float* Aptr = A + (m0 + lrow) * E_ + lk;
    const float* Wptr = W + (n0 + lrow) * E_ + lk;

    for (int k0 = 0; k0 < E_; k0 += BK) {
        float4 av = *(const float4*)(Aptr + k0);
        float4 bv = *(const float4*)(Wptr + k0);
        __syncthreads();
        As[lk + 0][lrow] = av.x; As[lk + 1][lrow] = av.y;
        As[lk + 2][lrow] = av.z; As[lk + 3][lrow] = av.w;
        Bs[lk + 0][lrow] = bv.x; Bs[lk + 1][lrow] = bv.y;
        Bs[lk + 2][lrow] = bv.z; Bs[lk + 3][lrow] = bv.w;
        __syncthreads();

        #pragma unroll
        for (int k = 0; k < BK; k++) {
            float a[4], b[4];
            #pragma unroll
            for (int i = 0; i < 4; i++) a[i] = As[k][ty * 4 + i];
            #pragma unroll
            for (int j = 0; j < 4; j++) b[j] = Bs[k][tx * 4 + j];
            #pragma unroll
            for (int i = 0; i < 4; i++)
                #pragma unroll
                for (int j = 0; j < 4; j++)
                    acc[i][j] = fmaf(a[i], b[j], acc[i][j]);
        }
    }

    #pragma unroll
    for (int i = 0; i < 4; i++) {
        int m = m0 + ty * 4 + i;
        #pragma unroll
        for (int j = 0; j < 4; j++) {
            int n = n0 + tx * 4 + j;
            if (HEAD_LAYOUT) {
                int b = m >> 11;          // m / S_
                int s = m & (S_ - 1);
                int h = n >> 6;           // n / D_
                int d = n & (D_ - 1);
                C[((b * H_ + h) * S_ + s) * D_ + d] = acc[i][j];
            } else {
                C[m * E_ + n] = acc[i][j];
            }
        }
    }
}

// ---------------------------------------------------------------------------
// Flash attention: one thread per query row; 128 queries per block.
// K/V tiles of 64 keys staged in dynamic smem; online softmax.
// grid = (S/128, B*H), block = 128 threads.
// ---------------------------------------------------------------------------
#define QT 128
#define KT 64

__global__ __launch_bounds__(QT)
void attn_kernel()
{
    extern __shared__ float sm[];
    float* sK = sm;                        // KT*D_ = 4096 floats
    float* sV = sm + KT * D_;              // 4096 floats
    float* sS = sm + 2 * KT * D_;          // QT*(KT+1) = 8320 floats

    const int t  = threadIdx.x;            // query within block
    const int bh = blockIdx.y;             // 0..B*H-1
    const int q0 = blockIdx.x * QT;

    // Load this thread's query row into registers
    float q[D_];
    const float4* Qv = (const float4*)(g_q + (size_t)(bh * S_ + q0 + t) * D_);
    #pragma unroll
    for (int i = 0; i < D_ / 4; i++) {
        float4 v = Qv[i];
        q[4 * i + 0] = v.x; q[4 * i + 1] = v.y;
        q[4 * i + 2] = v.z; q[4 * i + 3] = v.w;
    }

    float mrun = -1e30f, l = 0.0f;
    float acc[D_];
    #pragma unroll
    for (int d = 0; d < D_; d++) acc[d] = 0.0f;

    const float* Kb = g_k + (size_t)bh * S_ * D_;
    const float* Vb = g_v + (size_t)bh * S_ * D_;

    for (int j0 = 0; j0 < S_; j0 += KT) {
        __syncthreads();
        // Cooperative coalesced tile load (tile is a contiguous 16KB chunk)
        const float4* Ks = (const float4*)(Kb + (size_t)j0 * D_);
        const float4* Vs = (const float4*)(Vb + (size_t)j0 * D_);
        #pragma unroll
        for (int i = 0; i < (KT * D_ / 4) / QT; i++) {
            ((float4*)sK)[t + i * QT] = Ks[t + i * QT];
            ((float4*)sV)[t + i * QT] = Vs[t + i * QT];
        }
        __syncthreads();

        // Pass 1: scores + tile max
        float tm = -1e30f;
        for (int kk = 0; kk < KT; kk++) {
            float s0 = 0.f, s1 = 0.f, s2 = 0.f, s3 = 0.f;
            const float* Krow = sK + kk * D_;
            #pragma unroll
            for (int d = 0; d < D_; d += 4) {
                s0 = fmaf(q[d + 0], Krow[d + 0], s0);
                s1 = fmaf(q[d + 1], Krow[d + 1], s1);
                s2 = fmaf(q[d + 2], Krow[d + 2], s2);
                s3 = fmaf(q[d + 3], Krow[d + 3], s3);
            }
            float s = ((s0 + s1) + (s2 + s3)) * SCALE_;
            sS[t * (KT + 1) + kk] = s;
            tm = fmaxf(tm, s);
        }

        // Online softmax rescale
        float nm = fmaxf(mrun, tm);
        float cf = __expf(mrun - nm);
        l *= cf;
        #pragma unroll
        for (int d = 0; d < D_; d++) acc[d] *= cf;

        // Pass 2: exp + accumulate P@V
        for (int kk = 0; kk < KT; kk++) {
            float p = __expf(sS[t * (KT + 1) + kk] - nm);
            l += p;
            const float* Vrow = sV + kk * D_;
            #pragma unroll
            for (int d = 0; d < D_; d++)
                acc[d] = fmaf(p, Vrow[d], acc[d]);
        }
        mrun = nm;
    }

    // Write merged-head layout [B,S,E]
    const int b = bh / H_;
    const int h = bh % H_;
    float inv = 1.0f / l;
    float* Ob = g_att + ((size_t)(b * S_ + q0 + t) * E_) + h * D_;
    #pragma unroll
    for (int d = 0; d < D_; d += 4) {
        float4 v;
        v.x = acc[d + 0] * inv; v.y = acc[d + 1] * inv;
        v.z = acc[d + 2] * inv; v.w = acc[d + 3] * inv;
        *(float4*)(Ob + d) = v;
    }
}

// ---------------------------------------------------------------------------
// Launch
// ---------------------------------------------------------------------------
extern "C" void kernel_launch(void* const* d_in, const int* in_sizes, int n_in,
                              void* d_out, int out_size)
{
    (void)in_sizes; (void)n_in; (void)out_size;
    const float* x  = (const float*)d_in[0];
    const float* wq = (const float*)d_in[1];
    const float* wk = (const float*)d_in[2];
    const float* wv = (const float*)d_in[3];
    const float* wo = (const float*)d_in[4];
    float* out = (float*)d_out;

    float *pq, *pk, *pv, *pa;
    cudaGetSymbolAddress((void**)&pq, g_q);
    cudaGetSymbolAddress((void**)&pk, g_k);
    cudaGetSymbolAddress((void**)&pv, g_v);
    cudaGetSymbolAddress((void**)&pa, g_att);

    dim3 gp(E_ / 64, M_ / 64);   // (16, 64)

    gemm_nt_kernel<true><<<gp, 256>>>(x, wq, pq);
    gemm_nt_kernel<true><<<gp, 256>>>(x, wk, pk);
    gemm_nt_kernel<true><<<gp, 256>>>(x, wv, pv);

    int smem_bytes = (2 * KT * D_ + QT * (KT + 1)) * (int)sizeof(float); // 66048
    cudaFuncSetAttribute(attn_kernel, cudaFuncAttributeMaxDynamicSharedMemorySize,
                         smem_bytes);
    attn_kernel<<<dim3(S_ / QT, B_ * H_), QT, smem_bytes>>>();

    gemm_nt_kernel<false><<<gp, 256>>>(pa, wo, out);
}

// round 2
// speedup vs baseline: 1.3965x; 1.3965x over previous
#include <cuda_runtime.h>
#include <math.h>
#include <stdint.h>

#define B_ 2
#define S_ 2048
#define E_ 1024
#define H_ 16
#define D_ 64
#define M_ (B_*S_)
#define SCALE_ 0.125f

__device__ float g_q[B_*H_*S_*D_];
__device__ float g_k[B_*H_*S_*D_];
__device__ float g_v[B_*H_*S_*D_];
__device__ float g_att[B_*S_*E_];

// ---------------------------------------------------------------------------
// tf32 helpers
// ---------------------------------------------------------------------------
__device__ __forceinline__ uint32_t f2tf32(float x) {
    uint32_t r;
    asm("cvt.rna.tf32.f32 %0, %1;" : "=r"(r) : "f"(x));
    return r;
}

__device__ __forceinline__ void mma_tf32(float c[4], const uint32_t a[4],
                                         const uint32_t b[2]) {
    asm volatile(
        "mma.sync.aligned.m16n8k8.row.col.f32.tf32.tf32.f32 "
        "{%0,%1,%2,%3}, {%4,%5,%6,%7}, {%8,%9}, {%0,%1,%2,%3};"
        : "+f"(c[0]), "+f"(c[1]), "+f"(c[2]), "+f"(c[3])
        : "r"(a[0]), "r"(a[1]), "r"(a[2]), "r"(a[3]), "r"(b[0]), "r"(b[1]));
}

// ---------------------------------------------------------------------------
// tf32 tensor-core GEMM: C[m][n] = sum_k A[m][k] * W[n][k]
// BM=128, BN=64, BK=16. 256 threads = 8 warps in 4(m) x 2(n); 32x32 warp tile.
// smem row stride 20 floats -> conflict-free fragment loads.
// ---------------------------------------------------------------------------
#define BM 128
#define BN 64
#define BK 16
#define LDS_STRIDE 20

template<bool HEAD_LAYOUT>
__global__ __launch_bounds__(256)
void gemm_tf32_kernel(const float* __restrict__ A, const float* __restrict__ W,
                      float* __restrict__ C)
{
    __shared__ uint32_t As[BM * LDS_STRIDE];
    __shared__ uint32_t Ws[BN * LDS_STRIDE];

    const int tid  = threadIdx.x;
    const int wid  = tid >> 5;
    const int lane = tid & 31;
    const int g    = lane >> 2;      // groupID 0..7
    const int t    = lane & 3;       // thread-in-group 0..3
    const int wm   = (wid & 3) * 32; // warp m offset in tile
    const int wn   = (wid >> 2) * 32;
    const int m0   = blockIdx.y * BM;
    const int n0   = blockIdx.x * BN;

    // global load roles
    const int lr = tid >> 2;        // 0..63
    const int lq = (tid & 3) * 4;   // k quad offset 0,4,8,12

    float acc[2][4][4];
    #pragma unroll
    for (int mi = 0; mi < 2; mi++)
        #pragma unroll
        for (int ni = 0; ni < 4; ni++)
            #pragma unroll
            for (int r = 0; r < 4; r++) acc[mi][ni][r] = 0.0f;

    const float* Abase0 = A + (size_t)(m0 + lr) * E_ + lq;
    const float* Abase1 = A + (size_t)(m0 + 64 + lr) * E_ + lq;
    const float* Wbase  = W + (size_t)(n0 + lr) * E_ + lq;

    float4 pa0 = *(const float4*)(Abase0);
    float4 pa1 = *(const float4*)(Abase1);
    float4 pw  = *(const float4*)(Wbase);

    for (int k0 = 0; k0 < E_; k0 += BK) {
        // store prefetched tile (convert to tf32)
        uint32_t* as0 = &As[lr * LDS_STRIDE + lq];
        uint32_t* as1 = &As[(64 + lr) * LDS_STRIDE + lq];
        uint32_t* ws  = &Ws[lr * LDS_STRIDE + lq];
        as0[0] = f2tf32(pa0.x); as0[1] = f2tf32(pa0.y);
        as0[2] = f2tf32(pa0.z); as0[3] = f2tf32(pa0.w);
        as1[0] = f2tf32(pa1.x); as1[1] = f2tf32(pa1.y);
        as1[2] = f2tf32(pa1.z); as1[3] = f2tf32(pa1.w);
        ws[0]  = f2tf32(pw.x);  ws[1]  = f2tf32(pw.y);
        ws[2]  = f2tf32(pw.z);  ws[3]  = f2tf32(pw.w);
        __syncthreads();

        // prefetch next tile
        if (k0 + BK < E_) {
            pa0 = *(const float4*)(Abase0 + k0 + BK);
            pa1 = *(const float4*)(Abase1 + k0 + BK);
            pw  = *(const float4*)(Wbase  + k0 + BK);
        }

        // compute: 2 k8 steps
        #pragma unroll
        for (int ks = 0; ks < 2; ks++) {
            const int kb = ks * 8;
            uint32_t a[2][4];
            #pragma unroll
            for (int mi = 0; mi < 2; mi++) {
                const int mr = wm + mi * 16;
                a[mi][0] = As[(mr + g)     * LDS_STRIDE + kb + t];
                a[mi][1] = As[(mr + g + 8) * LDS_STRIDE + kb + t];
                a[mi][2] = As[(mr + g)     * LDS_STRIDE + kb + t + 4];
                a[mi][3] = As[(mr + g + 8) * LDS_STRIDE + kb + t + 4];
            }
            uint32_t b[4][2];
            #pragma unroll
            for (int ni = 0; ni < 4; ni++) {
                const int nc = wn + ni * 8;
                b[ni][0] = Ws[(nc + g) * LDS_STRIDE + kb + t];
                b[ni][1] = Ws[(nc + g) * LDS_STRIDE + kb + t + 4];
            }
            #pragma unroll
            for (int mi = 0; mi < 2; mi++)
                #pragma unroll
                for (int ni = 0; ni < 4; ni++)
                    mma_tf32(acc[mi][ni], a[mi], b[ni]);
        }
        __syncthreads();
    }

    // epilogue
    #pragma unroll
    for (int mi = 0; mi < 2; mi++) {
        #pragma unroll
        for (int ni = 0; ni < 4; ni++) {
            const int col = n0 + wn + ni * 8 + 2 * t;
            #pragma unroll
            for (int half = 0; half < 2; half++) {
                const int row = m0 + wm + mi * 16 + g + half * 8;
                float2 v;
                v.x = acc[mi][ni][half * 2 + 0];
                v.y = acc[mi][ni][half * 2 + 1];
                if (HEAD_LAYOUT) {
                    const int b = row >> 11;
                    const int s = row & (S_ - 1);
                    const int h = col >> 6;
                    const int d = col & (D_ - 1);
                    *(float2*)(C + ((size_t)(b * H_ + h) * S_ + s) * D_ + d) = v;
                } else {
                    *(float2*)(C + (size_t)row * E_ + col) = v;
                }
            }
        }
    }
}

// ---------------------------------------------------------------------------
// Flash attention (unchanged fp32 SIMT this round)
// ---------------------------------------------------------------------------
#define QT 128
#define KT 64

__global__ __launch_bounds__(QT)
void attn_kernel()
{
    extern __shared__ float sm[];
    float* sK = sm;
    float* sV = sm + KT * D_;
    float* sS = sm + 2 * KT * D_;

    const int t  = threadIdx.x;
    const int bh = blockIdx.y;
    const int q0 = blockIdx.x * QT;

    float q[D_];
    const float4* Qv = (const float4*)(g_q + (size_t)(bh * S_ + q0 + t) * D_);
    #pragma unroll
    for (int i = 0; i < D_ / 4; i++) {
        float4 v = Qv[i];
        q[4 * i + 0] = v.x; q[4 * i + 1] = v.y;
        q[4 * i + 2] = v.z; q[4 * i + 3] = v.w;
    }

    float mrun = -1e30f, l = 0.0f;
    float acc[D_];
    #pragma unroll
    for (int d = 0; d < D_; d++) acc[d] = 0.0f;

    const float* Kb = g_k + (size_t)bh * S_ * D_;
    const float* Vb = g_v + (size_t)bh * S_ * D_;

    for (int j0 = 0; j0 < S_; j0 += KT) {
        __syncthreads();
        const float4* Ks = (const float4*)(Kb + (size_t)j0 * D_);
        const float4* Vs = (const float4*)(Vb + (size_t)j0 * D_);
        #pragma unroll
        for (int i = 0; i < (KT * D_ / 4) / QT; i++) {
            ((float4*)sK)[t + i * QT] = Ks[t + i * QT];
            ((float4*)sV)[t + i * QT] = Vs[t + i * QT];
        }
        __syncthreads();

        float tm = -1e30f;
        for (int kk = 0; kk < KT; kk++) {
            float s0 = 0.f, s1 = 0.f, s2 = 0.f, s3 = 0.f;
            const float* Krow = sK + kk * D_;
            #pragma unroll
            for (int d = 0; d < D_; d += 4) {
                s0 = fmaf(q[d + 0], Krow[d + 0], s0);
                s1 = fmaf(q[d + 1], Krow[d + 1], s1);
                s2 = fmaf(q[d + 2], Krow[d + 2], s2);
                s3 = fmaf(q[d + 3], Krow[d + 3], s3);
            }
            float s = ((s0 + s1) + (s2 + s3)) * SCALE_;
            sS[t * (KT + 1) + kk] = s;
            tm = fmaxf(tm, s);
        }

        float nm = fmaxf(mrun, tm);
        float cf = __expf(mrun - nm);
        l *= cf;
        #pragma unroll
        for (int d = 0; d < D_; d++) acc[d] *= cf;

        for (int kk = 0; kk < KT; kk++) {
            float p = __expf(sS[t * (KT + 1) + kk] - nm);
            l += p;
            const float* Vrow = sV + kk * D_;
            #pragma unroll
            for (int d = 0; d < D_; d++)
                acc[d] = fmaf(p, Vrow[d], acc[d]);
        }
        mrun = nm;
    }

    const int b = bh / H_;
    const int h = bh % H_;
    float inv = 1.0f / l;
    float* Ob = g_att + ((size_t)(b * S_ + q0 + t) * E_) + h * D_;
    #pragma unroll
    for (int d = 0; d < D_; d += 4) {
        float4 v;
        v.x = acc[d + 0] * inv; v.y = acc[d + 1] * inv;
        v.z = acc[d + 2] * inv; v.w = acc[d + 3] * inv;
        *(float4*)(Ob + d) = v;
    }
}

// ---------------------------------------------------------------------------
// Launch
// ---------------------------------------------------------------------------
extern "C" void kernel_launch(void* const* d_in, const int* in_sizes, int n_in,
                              void* d_out, int out_size)
{
    (void)in_sizes; (void)n_in; (void)out_size;
    const float* x  = (const float*)d_in[0];
    const float* wq = (const float*)d_in[1];
    const float* wk = (const float*)d_in[2];
    const float* wv = (const float*)d_in[3];
    const float* wo = (const float*)d_in[4];
    float* out = (float*)d_out;

    float *pq, *pk, *pv, *pa;
    cudaGetSymbolAddress((void**)&pq, g_q);
    cudaGetSymbolAddress((void**)&pk, g_k);
    cudaGetSymbolAddress((void**)&pv, g_v);
    cudaGetSymbolAddress((void**)&pa, g_att);

    dim3 gp(E_ / BN, M_ / BM);   // (16, 32)

    gemm_tf32_kernel<true><<<gp, 256>>>(x, wq, pq);
    gemm_tf32_kernel<true><<<gp, 256>>>(x, wk, pk);
    gemm_tf32_kernel<true><<<gp, 256>>>(x, wv, pv);

    int smem_bytes = (2 * KT * D_ + QT * (KT + 1)) * (int)sizeof(float);
    cudaFuncSetAttribute(attn_kernel, cudaFuncAttributeMaxDynamicSharedMemorySize,
                         smem_bytes);
    attn_kernel<<<dim3(S_ / QT, B_ * H_), QT, smem_bytes>>>();

    gemm_tf32_kernel<false><<<gp, 256>>>(pa, wo, out);
}

// round 3
// speedup vs baseline: 3.6296x; 2.5991x over previous
#include <cuda_runtime.h>
#include <math.h>
#include <stdint.h>

#define B_ 2
#define S_ 2048
#define E_ 1024
#define H_ 16
#define D_ 64
#define M_ (B_*S_)
#define SCALE_ 0.125f

__device__ float g_q[B_*H_*S_*D_];
__device__ float g_k[B_*H_*S_*D_];
__device__ float g_v[B_*H_*S_*D_];
__device__ float g_att[B_*S_*E_];

// ---------------------------------------------------------------------------
// tf32 helpers
// ---------------------------------------------------------------------------
__device__ __forceinline__ uint32_t f2tf32(float x) {
    uint32_t r;
    asm("cvt.rna.tf32.f32 %0, %1;" : "=r"(r) : "f"(x));
    return r;
}

__device__ __forceinline__ void mma_tf32(float c[4], const uint32_t a[4],
                                         const uint32_t b[2]) {
    asm volatile(
        "mma.sync.aligned.m16n8k8.row.col.f32.tf32.tf32.f32 "
        "{%0,%1,%2,%3}, {%4,%5,%6,%7}, {%8,%9}, {%0,%1,%2,%3};"
        : "+f"(c[0]), "+f"(c[1]), "+f"(c[2]), "+f"(c[3])
        : "r"(a[0]), "r"(a[1]), "r"(a[2]), "r"(a[3]), "r"(b[0]), "r"(b[1]));
}

// ---------------------------------------------------------------------------
// tf32 tensor-core GEMM (unchanged from R2)
// ---------------------------------------------------------------------------
#define BM 128
#define BN 64
#define BK 16
#define LDS_STRIDE 20

template<bool HEAD_LAYOUT>
__global__ __launch_bounds__(256)
void gemm_tf32_kernel(const float* __restrict__ A, const float* __restrict__ W,
                      float* __restrict__ C)
{
    __shared__ uint32_t As[BM * LDS_STRIDE];
    __shared__ uint32_t Ws[BN * LDS_STRIDE];

    const int tid  = threadIdx.x;
    const int wid  = tid >> 5;
    const int lane = tid & 31;
    const int g    = lane >> 2;
    const int t    = lane & 3;
    const int wm   = (wid & 3) * 32;
    const int wn   = (wid >> 2) * 32;
    const int m0   = blockIdx.y * BM;
    const int n0   = blockIdx.x * BN;

    const int lr = tid >> 2;
    const int lq = (tid & 3) * 4;

    float acc[2][4][4];
    #pragma unroll
    for (int mi = 0; mi < 2; mi++)
        #pragma unroll
        for (int ni = 0; ni < 4; ni++)
            #pragma unroll
            for (int r = 0; r < 4; r++) acc[mi][ni][r] = 0.0f;

    const float* Abase0 = A + (size_t)(m0 + lr) * E_ + lq;
    const float* Abase1 = A + (size_t)(m0 + 64 + lr) * E_ + lq;
    const float* Wbase  = W + (size_t)(n0 + lr) * E_ + lq;

    float4 pa0 = *(const float4*)(Abase0);
    float4 pa1 = *(const float4*)(Abase1);
    float4 pw  = *(const float4*)(Wbase);

    for (int k0 = 0; k0 < E_; k0 += BK) {
        uint32_t* as0 = &As[lr * LDS_STRIDE + lq];
        uint32_t* as1 = &As[(64 + lr) * LDS_STRIDE + lq];
        uint32_t* ws  = &Ws[lr * LDS_STRIDE + lq];
        as0[0] = f2tf32(pa0.x); as0[1] = f2tf32(pa0.y);
        as0[2] = f2tf32(pa0.z); as0[3] = f2tf32(pa0.w);
        as1[0] = f2tf32(pa1.x); as1[1] = f2tf32(pa1.y);
        as1[2] = f2tf32(pa1.z); as1[3] = f2tf32(pa1.w);
        ws[0]  = f2tf32(pw.x);  ws[1]  = f2tf32(pw.y);
        ws[2]  = f2tf32(pw.z);  ws[3]  = f2tf32(pw.w);
        __syncthreads();

        if (k0 + BK < E_) {
            pa0 = *(const float4*)(Abase0 + k0 + BK);
            pa1 = *(const float4*)(Abase1 + k0 + BK);
            pw  = *(const float4*)(Wbase  + k0 + BK);
        }

        #pragma unroll
        for (int ks = 0; ks < 2; ks++) {
            const int kb = ks * 8;
            uint32_t a[2][4];
            #pragma unroll
            for (int mi = 0; mi < 2; mi++) {
                const int mr = wm + mi * 16;
                a[mi][0] = As[(mr + g)     * LDS_STRIDE + kb + t];
                a[mi][1] = As[(mr + g + 8) * LDS_STRIDE + kb + t];
                a[mi][2] = As[(mr + g)     * LDS_STRIDE + kb + t + 4];
                a[mi][3] = As[(mr + g + 8) * LDS_STRIDE + kb + t + 4];
            }
            uint32_t b[4][2];
            #pragma unroll
            for (int ni = 0; ni < 4; ni++) {
                const int nc = wn + ni * 8;
                b[ni][0] = Ws[(nc + g) * LDS_STRIDE + kb + t];
                b[ni][1] = Ws[(nc + g) * LDS_STRIDE + kb + t + 4];
            }
            #pragma unroll
            for (int mi = 0; mi < 2; mi++)
                #pragma unroll
                for (int ni = 0; ni < 4; ni++)
                    mma_tf32(acc[mi][ni], a[mi], b[ni]);
        }
        __syncthreads();
    }

    #pragma unroll
    for (int mi = 0; mi < 2; mi++) {
        #pragma unroll
        for (int ni = 0; ni < 4; ni++) {
            const int col = n0 + wn + ni * 8 + 2 * t;
            #pragma unroll
            for (int half = 0; half < 2; half++) {
                const int row = m0 + wm + mi * 16 + g + half * 8;
                float2 v;
                v.x = acc[mi][ni][half * 2 + 0];
                v.y = acc[mi][ni][half * 2 + 1];
                if (HEAD_LAYOUT) {
                    const int b = row >> 11;
                    const int s = row & (S_ - 1);
                    const int h = col >> 6;
                    const int d = col & (D_ - 1);
                    *(float2*)(C + ((size_t)(b * H_ + h) * S_ + s) * D_ + d) = v;
                } else {
                    *(float2*)(C + (size_t)row * E_ + col) = v;
                }
            }
        }
    }
}

// ---------------------------------------------------------------------------
// Tensor-core flash attention (tf32 MMA).
// Block: 128 q-rows, 256 threads (8 warps x 16 rows). KV tiles of 64 keys.
// K smem stride 68 -> b-frag banks 4g+t (conflict-free).
// V smem stride 72 -> b-frag banks 8t+g (conflict-free).
// ---------------------------------------------------------------------------
#define AQT 128
#define AKT 64
#define KST 68
#define VST 72

__global__ __launch_bounds__(256)
void attn_mma_kernel()
{
    __shared__ uint32_t sK[AKT * KST];   // tf32 bit patterns
    __shared__ uint32_t sV[AKT * VST];

    const int tid  = threadIdx.x;
    const int w    = tid >> 5;
    const int lane = tid & 31;
    const int g    = lane >> 2;
    const int t    = lane & 3;
    const int bh   = blockIdx.y;
    const int q0   = blockIdx.x * AQT;
    const int qrow = q0 + w * 16;

    // Q fragments: 16 rows x 64 cols, pre-scaled, loaded once.
    uint32_t aq[8][4];
    {
        const float* Qb = g_q + ((size_t)bh * S_ + qrow) * D_;
        #pragma unroll
        for (int kc = 0; kc < 8; kc++) {
            aq[kc][0] = f2tf32(Qb[(g    ) * D_ + kc * 8 + t    ] * SCALE_);
            aq[kc][1] = f2tf32(Qb[(g + 8) * D_ + kc * 8 + t    ] * SCALE_);
            aq[kc][2] = f2tf32(Qb[(g    ) * D_ + kc * 8 + t + 4] * SCALE_);
            aq[kc][3] = f2tf32(Qb[(g + 8) * D_ + kc * 8 + t + 4] * SCALE_);
        }
    }

    float oacc[8][4];
    #pragma unroll
    for (int ni = 0; ni < 8; ni++)
        #pragma unroll
        for (int r = 0; r < 4; r++) oacc[ni][r] = 0.0f;

    float mA = -1e30f, mB = -1e30f, lA = 0.0f, lB = 0.0f;

    const float* Kb = g_k + (size_t)bh * S_ * D_;
    const float* Vb = g_v + (size_t)bh * S_ * D_;

    // prefetch tile 0 (64x64 floats = 1024 float4, 4 per thread)
    float4 pk[4], pv[4];
    #pragma unroll
    for (int i = 0; i < 4; i++) {
        pk[i] = ((const float4*)Kb)[tid + i * 256];
        pv[i] = ((const float4*)Vb)[tid + i * 256];
    }

    for (int j0 = 0; j0 < S_; j0 += AKT) {
        __syncthreads();
        #pragma unroll
        for (int i = 0; i < 4; i++) {
            const int idx = tid + i * 256;
            const int r = idx >> 4, c4 = (idx & 15) * 4;
            uint32_t* dk = &sK[r * KST + c4];
            uint32_t* dv = &sV[r * VST + c4];
            dk[0] = f2tf32(pk[i].x); dk[1] = f2tf32(pk[i].y);
            dk[2] = f2tf32(pk[i].z); dk[3] = f2tf32(pk[i].w);
            dv[0] = f2tf32(pv[i].x); dv[1] = f2tf32(pv[i].y);
            dv[2] = f2tf32(pv[i].z); dv[3] = f2tf32(pv[i].w);
        }
        __syncthreads();

        if (j0 + AKT < S_) {
            const float4* Kn = (const float4*)(Kb + (size_t)(j0 + AKT) * D_);
            const float4* Vn = (const float4*)(Vb + (size_t)(j0 + AKT) * D_);
            #pragma unroll
            for (int i = 0; i < 4; i++) {
                pk[i] = Kn[tid + i * 256];
                pv[i] = Vn[tid + i * 256];
            }
        }

        // ---- scores: S = Q K^T (16 x 64 per warp) ----
        float sc[8][4];
        #pragma unroll
        for (int ni = 0; ni < 8; ni++)
            #pragma unroll
            for (int r = 0; r < 4; r++) sc[ni][r] = 0.0f;

        #pragma unroll
        for (int kc = 0; kc < 8; kc++) {
            #pragma unroll
            for (int ni = 0; ni < 8; ni++) {
                uint32_t b[2];
                b[0] = sK[(ni * 8 + g) * KST + kc * 8 + t];
                b[1] = sK[(ni * 8 + g) * KST + kc * 8 + t + 4];
                mma_tf32(sc[ni], aq[kc], b);
            }
        }

        // ---- online softmax ----
        float rmA = -1e30f, rmB = -1e30f;
        #pragma unroll
        for (int ni = 0; ni < 8; ni++) {
            rmA = fmaxf(rmA, fmaxf(sc[ni][0], sc[ni][1]));
            rmB = fmaxf(rmB, fmaxf(sc[ni][2], sc[ni][3]));
        }
        rmA = fmaxf(rmA, __shfl_xor_sync(0xffffffffu, rmA, 1));
        rmA = fmaxf(rmA, __shfl_xor_sync(0xffffffffu, rmA, 2));
        rmB = fmaxf(rmB, __shfl_xor_sync(0xffffffffu, rmB, 1));
        rmB = fmaxf(rmB, __shfl_xor_sync(0xffffffffu, rmB, 2));

        const float nmA = fmaxf(mA, rmA);
        const float nmB = fmaxf(mB, rmB);
        const float cfA = __expf(mA - nmA);
        const float cfB = __expf(mB - nmB);
        mA = nmA; mB = nmB;

        float rsA = 0.0f, rsB = 0.0f;
        #pragma unroll
        for (int ni = 0; ni < 8; ni++) {
            sc[ni][0] = __expf(sc[ni][0] - mA); rsA += sc[ni][0];
            sc[ni][1] = __expf(sc[ni][1] - mA); rsA += sc[ni][1];
            sc[ni][2] = __expf(sc[ni][2] - mB); rsB += sc[ni][2];
            sc[ni][3] = __expf(sc[ni][3] - mB); rsB += sc[ni][3];
        }
        rsA += __shfl_xor_sync(0xffffffffu, rsA, 1);
        rsA += __shfl_xor_sync(0xffffffffu, rsA, 2);
        rsB += __shfl_xor_sync(0xffffffffu, rsB, 1);
        rsB += __shfl_xor_sync(0xffffffffu, rsB, 2);
        lA = lA * cfA + rsA;
        lB = lB * cfB + rsB;

        #pragma unroll
        for (int ni = 0; ni < 8; ni++) {
            oacc[ni][0] *= cfA; oacc[ni][1] *= cfA;
            oacc[ni][2] *= cfB; oacc[ni][3] *= cfB;
        }

        // ---- O += P V ----
        // Remap P accumulator layout (cols {2t,2t+1}) to A-operand layout
        // (cols {t,t+4}) via intra-quad shuffles.
        const int src0 = (lane & ~3) | (t >> 1);
        const int src1 = src0 + 2;
        #pragma unroll
        for (int kc = 0; kc < 8; kc++) {
            const float q00 = __shfl_sync(0xffffffffu, sc[kc][0], src0);
            const float q01 = __shfl_sync(0xffffffffu, sc[kc][1], src0);
            const float q10 = __shfl_sync(0xffffffffu, sc[kc][0], src1);
            const float q11 = __shfl_sync(0xffffffffu, sc[kc][1], src1);
            const float q20 = __shfl_sync(0xffffffffu, sc[kc][2], src0);
            const float q21 = __shfl_sync(0xffffffffu, sc[kc][3], src0);
            const float q30 = __shfl_sync(0xffffffffu, sc[kc][2], src1);
            const float q31 = __shfl_sync(0xffffffffu, sc[kc][3], src1);
            uint32_t ap[4];
            ap[0] = f2tf32((t & 1) ? q01 : q00);   // P(g,    t)
            ap[2] = f2tf32((t & 1) ? q11 : q10);   // P(g,    t+4)
            ap[1] = f2tf32((t & 1) ? q21 : q20);   // P(g+8,  t)
            ap[3] = f2tf32((t & 1) ? q31 : q30);   // P(g+8,  t+4)
            #pragma unroll
            for (int ni = 0; ni < 8; ni++) {
                uint32_t b[2];
                b[0] = sV[(kc * 8 + t    ) * VST + ni * 8 + g];
                b[1] = sV[(kc * 8 + t + 4) * VST + ni * 8 + g];
                mma_tf32(oacc[ni], ap, b);
            }
        }
    }

    // ---- epilogue: normalize and write merged-head [B,S,E] ----
    const float ivA = 1.0f / lA;
    const float ivB = 1.0f / lB;
    const int b = bh / H_;
    const int h = bh % H_;
    float* OA = g_att + ((size_t)(b * S_ + qrow + g    ) * E_) + h * D_;
    float* OB = g_att + ((size_t)(b * S_ + qrow + g + 8) * E_) + h * D_;
    #pragma unroll
    for (int ni = 0; ni < 8; ni++) {
        float2 va, vb;
        va.x = oacc[ni][0] * ivA; va.y = oacc[ni][1] * ivA;
        vb.x = oacc[ni][2] * ivB; vb.y = oacc[ni][3] * ivB;
        *(float2*)(OA + ni * 8 + 2 * t) = va;
        *(float2*)(OB + ni * 8 + 2 * t) = vb;
    }
}

// ---------------------------------------------------------------------------
// Launch
// ---------------------------------------------------------------------------
extern "C" void kernel_launch(void* const* d_in, const int* in_sizes, int n_in,
                              void* d_out, int out_size)
{
    (void)in_sizes; (void)n_in; (void)out_size;
    const float* x  = (const float*)d_in[0];
    const float* wq = (const float*)d_in[1];
    const float* wk = (const float*)d_in[2];
    const float* wv = (const float*)d_in[3];
    const float* wo = (const float*)d_in[4];
    float* out = (float*)d_out;

    float *pq, *pk, *pv, *pa;
    cudaGetSymbolAddress((void**)&pq, g_q);
    cudaGetSymbolAddress((void**)&pk, g_k);
    cudaGetSymbolAddress((void**)&pv, g_v);
    cudaGetSymbolAddress((void**)&pa, g_att);

    dim3 gp(E_ / BN, M_ / BM);   // (16, 32)

    gemm_tf32_kernel<true><<<gp, 256>>>(x, wq, pq);
    gemm_tf32_kernel<true><<<gp, 256>>>(x, wk, pk);
    gemm_tf32_kernel<true><<<gp, 256>>>(x, wv, pv);

    attn_mma_kernel<<<dim3(S_ / AQT, B_ * H_), 256>>>();

    gemm_tf32_kernel<false><<<gp, 256>>>(pa, wo, out);
}

// round 5
// speedup vs baseline: 4.4263x; 1.2195x over previous
#include <cuda_runtime.h>
#include <math.h>
#include <stdint.h>

#define B_ 2
#define S_ 2048
#define E_ 1024
#define H_ 16
#define D_ 64
#define M_ (B_*S_)
#define SCALE_ 0.125f
#define QSCALE_ 0.18033688011112042f   // SCALE_ * log2(e)

__device__ float g_q[B_*H_*S_*D_];
__device__ float g_k[B_*H_*S_*D_];
__device__ float g_v[B_*H_*S_*D_];
__device__ float g_att[B_*S_*E_];

// ---------------------------------------------------------------------------
// tf32 helpers
// ---------------------------------------------------------------------------
__device__ __forceinline__ uint32_t f2tf32(float x) {
    uint32_t r;
    asm("cvt.rna.tf32.f32 %0, %1;" : "=r"(r) : "f"(x));
    return r;
}

__device__ __forceinline__ void mma_tf32(float c[4], const uint32_t a[4],
                                         const uint32_t b[2]) {
    asm volatile(
        "mma.sync.aligned.m16n8k8.row.col.f32.tf32.tf32.f32 "
        "{%0,%1,%2,%3}, {%4,%5,%6,%7}, {%8,%9}, {%0,%1,%2,%3};"
        : "+f"(c[0]), "+f"(c[1]), "+f"(c[2]), "+f"(c[3])
        : "r"(a[0]), "r"(a[1]), "r"(a[2]), "r"(a[3]), "r"(b[0]), "r"(b[1]));
}

// ---------------------------------------------------------------------------
// tf32 GEMM: C[m][n] = sum_k A[m][k]*W[n][k]
// BM=64, BN=128, BK=16. 128 threads = 4 warps, each warp a 64x32 tile.
// QKV merged: blockIdx.z selects (W, C) pair. LDS stride 20 conflict-free.
// ---------------------------------------------------------------------------
#define GM 64
#define GN 128
#define GK 16
#define GST 20

template<bool HEAD_LAYOUT>
__global__ __launch_bounds__(128)
void gemm_tf32_kernel(const float* __restrict__ A,
                      const float* __restrict__ W0, const float* __restrict__ W1,
                      const float* __restrict__ W2,
                      float* __restrict__ C0, float* __restrict__ C1,
                      float* __restrict__ C2)
{
    __shared__ uint32_t As[GM * GST];
    __shared__ uint32_t Ws[GN * GST];

    const float* W = (blockIdx.z == 0) ? W0 : (blockIdx.z == 1) ? W1 : W2;
    float*       C = (blockIdx.z == 0) ? C0 : (blockIdx.z == 1) ? C1 : C2;

    const int tid  = threadIdx.x;
    const int wid  = tid >> 5;
    const int lane = tid & 31;
    const int g    = lane >> 2;
    const int t    = lane & 3;
    const int wn   = wid * 32;
    const int m0   = blockIdx.y * GM;
    const int n0   = blockIdx.x * GN;

    const int lr = tid >> 2;          // 0..31
    const int lq = (tid & 3) * 4;     // 0,4,8,12

    float acc[4][4][4];
    #pragma unroll
    for (int mi = 0; mi < 4; mi++)
        #pragma unroll
        for (int ni = 0; ni < 4; ni++)
            #pragma unroll
            for (int r = 0; r < 4; r++) acc[mi][ni][r] = 0.0f;

    const float* Ab = A + (size_t)(m0 + lr) * E_ + lq;
    const float* Wb = W + (size_t)(n0 + lr) * E_ + lq;

    float4 pa[2], pw[4];
    #pragma unroll
    for (int i = 0; i < 2; i++) pa[i] = *(const float4*)(Ab + (size_t)(i * 32) * E_);
    #pragma unroll
    for (int i = 0; i < 4; i++) pw[i] = *(const float4*)(Wb + (size_t)(i * 32) * E_);

    for (int k0 = 0; k0 < E_; k0 += GK) {
        __syncthreads();
        #pragma unroll
        for (int i = 0; i < 2; i++) {
            uint32_t* d = &As[(lr + i * 32) * GST + lq];
            d[0] = f2tf32(pa[i].x); d[1] = f2tf32(pa[i].y);
            d[2] = f2tf32(pa[i].z); d[3] = f2tf32(pa[i].w);
        }
        #pragma unroll
        for (int i = 0; i < 4; i++) {
            uint32_t* d = &Ws[(lr + i * 32) * GST + lq];
            d[0] = f2tf32(pw[i].x); d[1] = f2tf32(pw[i].y);
            d[2] = f2tf32(pw[i].z); d[3] = f2tf32(pw[i].w);
        }
        __syncthreads();

        if (k0 + GK < E_) {
            #pragma unroll
            for (int i = 0; i < 2; i++)
                pa[i] = *(const float4*)(Ab + (size_t)(i * 32) * E_ + k0 + GK);
            #pragma unroll
            for (int i = 0; i < 4; i++)
                pw[i] = *(const float4*)(Wb + (size_t)(i * 32) * E_ + k0 + GK);
        }

        #pragma unroll
        for (int ks = 0; ks < 2; ks++) {
            const int kb = ks * 8;
            uint32_t a[4][4];
            #pragma unroll
            for (int mi = 0; mi < 4; mi++) {
                const int mr = mi * 16;
                a[mi][0] = As[(mr + g)     * GST + kb + t];
                a[mi][1] = As[(mr + g + 8) * GST + kb + t];
                a[mi][2] = As[(mr + g)     * GST + kb + t + 4];
                a[mi][3] = As[(mr + g + 8) * GST + kb + t + 4];
            }
            uint32_t b[4][2];
            #pragma unroll
            for (int ni = 0; ni < 4; ni++) {
                const int nc = wn + ni * 8;
                b[ni][0] = Ws[(nc + g) * GST + kb + t];
                b[ni][1] = Ws[(nc + g) * GST + kb + t + 4];
            }
            #pragma unroll
            for (int mi = 0; mi < 4; mi++)
                #pragma unroll
                for (int ni = 0; ni < 4; ni++)
                    mma_tf32(acc[mi][ni], a[mi], b[ni]);
        }
    }

    #pragma unroll
    for (int mi = 0; mi < 4; mi++) {
        #pragma unroll
        for (int ni = 0; ni < 4; ni++) {
            const int col = n0 + wn + ni * 8 + 2 * t;
            #pragma unroll
            for (int half = 0; half < 2; half++) {
                const int row = m0 + mi * 16 + g + half * 8;
                float2 v;
                v.x = acc[mi][ni][half * 2 + 0];
                v.y = acc[mi][ni][half * 2 + 1];
                if (HEAD_LAYOUT) {
                    const int b = row >> 11;
                    const int s = row & (S_ - 1);
                    const int h = col >> 6;
                    const int d = col & (D_ - 1);
                    *(float2*)(C + ((size_t)(b * H_ + h) * S_ + s) * D_ + d) = v;
                } else {
                    *(float2*)(C + (size_t)row * E_ + col) = v;
                }
            }
        }
    }
}

// ---------------------------------------------------------------------------
// Tensor-core flash attention, Q staged in smem (low-reg, 2 CTAs/SM).
// Block: 128 q-rows, 256 threads (8 warps x 16 rows). KV tiles of 64 keys.
// Q/K smem stride 68 (banks 4g+t conflict-free); V stride 72 (banks 8t+g).
// Softmax in log2 domain (scale*log2e folded into Q) -> raw EX2.
// ---------------------------------------------------------------------------
#define AQT 128
#define AKT 64
#define QST 68
#define KST 68
#define VST 72
#define SQ_WORDS (AQT * QST)
#define SK_WORDS (AKT * KST)
#define SV_WORDS (AKT * VST)
#define ATTN_SMEM ((SQ_WORDS + SK_WORDS + SV_WORDS) * 4)

__global__ __launch_bounds__(256, 2)
void attn_mma_kernel()
{
    extern __shared__ uint32_t dsm[];
    uint32_t* sQ = dsm;
    uint32_t* sK = dsm + SQ_WORDS;
    uint32_t* sV = dsm + SQ_WORDS + SK_WORDS;

    const int tid  = threadIdx.x;
    const int w    = tid >> 5;
    const int lane = tid & 31;
    const int g    = lane >> 2;
    const int t    = lane & 3;
    const int bh   = blockIdx.y;
    const int q0   = blockIdx.x * AQT;
    const int qrow = q0 + w * 16;

    // ---- stage Q tile (128x64) into smem, pre-scaled to log2 domain ----
    {
        const float4* Qg = (const float4*)(g_q + ((size_t)bh * S_ + q0) * D_);
        #pragma unroll
        for (int i = 0; i < 8; i++) {
            const int idx = tid + i * 256;          // 0..2047 float4s
            const int r = idx >> 4, c4 = (idx & 15) * 4;
            float4 v = Qg[idx];
            uint32_t* d = &sQ[r * QST + c4];
            d[0] = f2tf32(v.x * QSCALE_); d[1] = f2tf32(v.y * QSCALE_);
            d[2] = f2tf32(v.z * QSCALE_); d[3] = f2tf32(v.w * QSCALE_);
        }
    }

    float oacc[8][4];
    #pragma unroll
    for (int ni = 0; ni < 8; ni++)
        #pragma unroll
        for (int r = 0; r < 4; r++) oacc[ni][r] = 0.0f;

    float mA = -1e30f, mB = -1e30f, lA = 0.0f, lB = 0.0f;

    const float* Kb = g_k + (size_t)bh * S_ * D_;
    const float* Vb = g_v + (size_t)bh * S_ * D_;

    for (int j0 = 0; j0 < S_; j0 += AKT) {
        __syncthreads();   // previous tile fully consumed (and Q staged, 1st iter)
        {
            const float4* Kg = (const float4*)(Kb + (size_t)j0 * D_);
            const float4* Vg = (const float4*)(Vb + (size_t)j0 * D_);
            float4 tk[4], tv[4];
            #pragma unroll
            for (int i = 0; i < 4; i++) { tk[i] = Kg[tid + i * 256]; tv[i] = Vg[tid + i * 256]; }
            #pragma unroll
            for (int i = 0; i < 4; i++) {
                const int idx = tid + i * 256;
                const int r = idx >> 4, c4 = (idx & 15) * 4;
                uint32_t* dk = &sK[r * KST + c4];
                uint32_t* dv = &sV[r * VST + c4];
                dk[0] = f2tf32(tk[i].x); dk[1] = f2tf32(tk[i].y);
                dk[2] = f2tf32(tk[i].z); dk[3] = f2tf32(tk[i].w);
                dv[0] = f2tf32(tv[i].x); dv[1] = f2tf32(tv[i].y);
                dv[2] = f2tf32(tv[i].z); dv[3] = f2tf32(tv[i].w);
            }
        }
        __syncthreads();

        // ---- scores: S = Q K^T (16 x 64 per warp), log2 domain ----
        float sc[8][4];
        #pragma unroll
        for (int ni = 0; ni < 8; ni++)
            #pragma unroll
            for (int r = 0; r < 4; r++) sc[ni][r] = 0.0f;

        #pragma unroll
        for (int kc = 0; kc < 8; kc++) {
            uint32_t a[4];
            const int qr = w * 16;
            a[0] = sQ[(qr + g)     * QST + kc * 8 + t];
            a[1] = sQ[(qr + g + 8) * QST + kc * 8 + t];
            a[2] = sQ[(qr + g)     * QST + kc * 8 + t + 4];
            a[3] = sQ[(qr + g + 8) * QST + kc * 8 + t + 4];
            #pragma unroll
            for (int ni = 0; ni < 8; ni++) {
                uint32_t b[2];
                b[0] = sK[(ni * 8 + g) * KST + kc * 8 + t];
                b[1] = sK[(ni * 8 + g) * KST + kc * 8 + t + 4];
                mma_tf32(sc[ni], a, b);
            }
        }

        // ---- online softmax (base-2) ----
        float rmA = -1e30f, rmB = -1e30f;
        #pragma unroll
        for (int ni = 0; ni < 8; ni++) {
            rmA = fmaxf(rmA, fmaxf(sc[ni][0], sc[ni][1]));
            rmB = fmaxf(rmB, fmaxf(sc[ni][2], sc[ni][3]));
        }
        rmA = fmaxf(rmA, __shfl_xor_sync(0xffffffffu, rmA, 1));
        rmA = fmaxf(rmA, __shfl_xor_sync(0xffffffffu, rmA, 2));
        rmB = fmaxf(rmB, __shfl_xor_sync(0xffffffffu, rmB, 1));
        rmB = fmaxf(rmB, __shfl_xor_sync(0xffffffffu, rmB, 2));

        const float nmA = fmaxf(mA, rmA);
        const float nmB = fmaxf(mB, rmB);
        const float cfA = exp2f(mA - nmA);
        const float cfB = exp2f(mB - nmB);
        mA = nmA; mB = nmB;

        float rsA = 0.0f, rsB = 0.0f;
        #pragma unroll
        for (int ni = 0; ni < 8; ni++) {
            sc[ni][0] = exp2f(sc[ni][0] - mA); rsA += sc[ni][0];
            sc[ni][1] = exp2f(sc[ni][1] - mA); rsA += sc[ni][1];
            sc[ni][2] = exp2f(sc[ni][2] - mB); rsB += sc[ni][2];
            sc[ni][3] = exp2f(sc[ni][3] - mB); rsB += sc[ni][3];
        }
        rsA += __shfl_xor_sync(0xffffffffu, rsA, 1);
        rsA += __shfl_xor_sync(0xffffffffu, rsA, 2);
        rsB += __shfl_xor_sync(0xffffffffu, rsB, 1);
        rsB += __shfl_xor_sync(0xffffffffu, rsB, 2);
        lA = lA * cfA + rsA;
        lB = lB * cfB + rsB;

        #pragma unroll
        for (int ni = 0; ni < 8; ni++) {
            oacc[ni][0] *= cfA; oacc[ni][1] *= cfA;
            oacc[ni][2] *= cfB; oacc[ni][3] *= cfB;
        }

        // ---- O += P V (P remapped to A-operand layout via intra-quad shfl) ----
        const int src0 = (lane & ~3) | (t >> 1);
        const int src1 = src0 + 2;
        #pragma unroll
        for (int kc = 0; kc < 8; kc++) {
            const float q00 = __shfl_sync(0xffffffffu, sc[kc][0], src0);
            const float q01 = __shfl_sync(0xffffffffu, sc[kc][1], src0);
            const float q10 = __shfl_sync(0xffffffffu, sc[kc][0], src1);
            const float q11 = __shfl_sync(0xffffffffu, sc[kc][1], src1);
            const float q20 = __shfl_sync(0xffffffffu, sc[kc][2], src0);
            const float q21 = __shfl_sync(0xffffffffu, sc[kc][3], src0);
            const float q30 = __shfl_sync(0xffffffffu, sc[kc][2], src1);
            const float q31 = __shfl_sync(0xffffffffu, sc[kc][3], src1);
            uint32_t ap[4];
            ap[0] = f2tf32((t & 1) ? q01 : q00);
            ap[2] = f2tf32((t & 1) ? q11 : q10);
            ap[1] = f2tf32((t & 1) ? q21 : q20);
            ap[3] = f2tf32((t & 1) ? q31 : q30);
            #pragma unroll
            for (int ni = 0; ni < 8; ni++) {
                uint32_t b[2];
                b[0] = sV[(kc * 8 + t    ) * VST + ni * 8 + g];
                b[1] = sV[(kc * 8 + t + 4) * VST + ni * 8 + g];
                mma_tf32(oacc[ni], ap, b);
            }
        }
    }

    // ---- epilogue ----
    const float ivA = 1.0f / lA;
    const float ivB = 1.0f / lB;
    const int b = bh / H_;
    const int h = bh % H_;
    float* OA = g_att + ((size_t)(b * S_ + qrow + g    ) * E_) + h * D_;
    float* OB = g_att + ((size_t)(b * S_ + qrow + g + 8) * E_) + h * D_;
    #pragma unroll
    for (int ni = 0; ni < 8; ni++) {
        float2 va, vb;
        va.x = oacc[ni][0] * ivA; va.y = oacc[ni][1] * ivA;
        vb.x = oacc[ni][2] * ivB; vb.y = oacc[ni][3] * ivB;
        *(float2*)(OA + ni * 8 + 2 * t) = va;
        *(float2*)(OB + ni * 8 + 2 * t) = vb;
    }
}

// ---------------------------------------------------------------------------
// Launch
// ---------------------------------------------------------------------------
extern "C" void kernel_launch(void* const* d_in, const int* in_sizes, int n_in,
                              void* d_out, int out_size)
{
    (void)in_sizes; (void)n_in; (void)out_size;
    const float* x  = (const float*)d_in[0];
    const float* wq = (const float*)d_in[1];
    const float* wk = (const float*)d_in[2];
    const float* wv = (const float*)d_in[3];
    const float* wo = (const float*)d_in[4];
    float* out = (float*)d_out;

    float *pq, *pk, *pv, *pa;
    cudaGetSymbolAddress((void**)&pq, g_q);
    cudaGetSymbolAddress((void**)&pk, g_k);
    cudaGetSymbolAddress((void**)&pv, g_v);
    cudaGetSymbolAddress((void**)&pa, g_att);

    // merged QKV projections: grid.z selects weight/output
    gemm_tf32_kernel<true><<<dim3(E_ / GN, M_ / GM, 3), 128>>>(
        x, wq, wk, wv, pq, pk, pv);

    cudaFuncSetAttribute(attn_mma_kernel,
                         cudaFuncAttributeMaxDynamicSharedMemorySize, ATTN_SMEM);
    attn_mma_kernel<<<dim3(S_ / AQT, B_ * H_), 256, ATTN_SMEM>>>();

    gemm_tf32_kernel<false><<<dim3(E_ / GN, M_ / GM, 1), 128>>>(
        pa, wo, wo, wo, out, out, out);
}

// round 6
// speedup vs baseline: 4.9772x; 1.1245x over previous
#include <cuda_runtime.h>
#include <math.h>
#include <stdint.h>

#define B_ 2
#define S_ 2048
#define E_ 1024
#define H_ 16
#define D_ 64
#define M_ (B_*S_)
#define SCALE_ 0.125f
#define QSCALE_ 0.18033688011112042f   // SCALE_ * log2(e)

__device__ float g_q[B_*H_*S_*D_];
__device__ float g_k[B_*H_*S_*D_];
__device__ float g_v[B_*H_*S_*D_];
__device__ float g_att[B_*S_*E_];

// ---------------------------------------------------------------------------
// tf32 helpers
// ---------------------------------------------------------------------------
__device__ __forceinline__ uint32_t f2tf32(float x) {
    uint32_t r;
    asm("cvt.rna.tf32.f32 %0, %1;" : "=r"(r) : "f"(x));
    return r;
}

__device__ __forceinline__ void mma_tf32(float c[4], const uint32_t a[4],
                                         const uint32_t b[2]) {
    asm volatile(
        "mma.sync.aligned.m16n8k8.row.col.f32.tf32.tf32.f32 "
        "{%0,%1,%2,%3}, {%4,%5,%6,%7}, {%8,%9}, {%0,%1,%2,%3};"
        : "+f"(c[0]), "+f"(c[1]), "+f"(c[2]), "+f"(c[3])
        : "r"(a[0]), "r"(a[1]), "r"(a[2]), "r"(a[3]), "r"(b[0]), "r"(b[1]));
}

// ---------------------------------------------------------------------------
// tf32 GEMM: C[m][n] = sum_k A[m][k]*W[n][k]
// Block tile 128x128, BK=16. 128 threads = 4 warps in 2x2, each warp 64x64.
// Double-buffered smem, ONE __syncthreads per k-tile.
// LDS stride 20 words: conflict-free a/b fragment loads.
// ---------------------------------------------------------------------------
#define GM 128
#define GN 128
#define GK 16
#define GST 20
#define NKT (E_ / GK)

template<bool HEAD_LAYOUT>
__global__ __launch_bounds__(128)
void gemm_tf32_kernel(const float* __restrict__ A,
                      const float* __restrict__ W0, const float* __restrict__ W1,
                      const float* __restrict__ W2,
                      float* __restrict__ C0, float* __restrict__ C1,
                      float* __restrict__ C2)
{
    __shared__ uint32_t As[2][GM * GST];
    __shared__ uint32_t Ws[2][GN * GST];

    const float* W = (blockIdx.z == 0) ? W0 : (blockIdx.z == 1) ? W1 : W2;
    float*       C = (blockIdx.z == 0) ? C0 : (blockIdx.z == 1) ? C1 : C2;

    const int tid  = threadIdx.x;
    const int wid  = tid >> 5;
    const int lane = tid & 31;
    const int g    = lane >> 2;
    const int t    = lane & 3;
    const int wm   = (wid & 1) * 64;
    const int wn   = (wid >> 1) * 64;
    const int m0   = blockIdx.y * GM;
    const int n0   = blockIdx.x * GN;

    const int lr = tid >> 2;          // 0..31
    const int lq = (tid & 3) * 4;     // 0,4,8,12

    float acc[4][8][4];
    #pragma unroll
    for (int mi = 0; mi < 4; mi++)
        #pragma unroll
        for (int ni = 0; ni < 8; ni++)
            #pragma unroll
            for (int r = 0; r < 4; r++) acc[mi][ni][r] = 0.0f;

    // Each thread loads 4 A rows (lr+32i) and 4 W rows per k-tile.
    const float* Ab = A + (size_t)(m0 + lr) * E_ + lq;
    const float* Wb = W + (size_t)(n0 + lr) * E_ + lq;

    float4 pa[4], pw[4];
    #pragma unroll
    for (int i = 0; i < 4; i++) {
        pa[i] = *(const float4*)(Ab + (size_t)(i * 32) * E_);
        pw[i] = *(const float4*)(Wb + (size_t)(i * 32) * E_);
    }
    // store tile 0 into buffer 0
    #pragma unroll
    for (int i = 0; i < 4; i++) {
        uint32_t* da = &As[0][(lr + i * 32) * GST + lq];
        uint32_t* dw = &Ws[0][(lr + i * 32) * GST + lq];
        da[0] = f2tf32(pa[i].x); da[1] = f2tf32(pa[i].y);
        da[2] = f2tf32(pa[i].z); da[3] = f2tf32(pa[i].w);
        dw[0] = f2tf32(pw[i].x); dw[1] = f2tf32(pw[i].y);
        dw[2] = f2tf32(pw[i].z); dw[3] = f2tf32(pw[i].w);
    }
    __syncthreads();

    for (int kt = 0; kt < NKT; kt++) {
        const int cur = kt & 1;
        const bool more = (kt + 1) < NKT;
        if (more) {
            const int off = (kt + 1) * GK;
            #pragma unroll
            for (int i = 0; i < 4; i++) {
                pa[i] = *(const float4*)(Ab + (size_t)(i * 32) * E_ + off);
                pw[i] = *(const float4*)(Wb + (size_t)(i * 32) * E_ + off);
            }
        }

        #pragma unroll
        for (int ks = 0; ks < 2; ks++) {
            const int kb = ks * 8;
            uint32_t a[4][4];
            #pragma unroll
            for (int mi = 0; mi < 4; mi++) {
                const int mr = wm + mi * 16;
                a[mi][0] = As[cur][(mr + g)     * GST + kb + t];
                a[mi][1] = As[cur][(mr + g + 8) * GST + kb + t];
                a[mi][2] = As[cur][(mr + g)     * GST + kb + t + 4];
                a[mi][3] = As[cur][(mr + g + 8) * GST + kb + t + 4];
            }
            uint32_t b[8][2];
            #pragma unroll
            for (int ni = 0; ni < 8; ni++) {
                const int nc = wn + ni * 8;
                b[ni][0] = Ws[cur][(nc + g) * GST + kb + t];
                b[ni][1] = Ws[cur][(nc + g) * GST + kb + t + 4];
            }
            #pragma unroll
            for (int mi = 0; mi < 4; mi++)
                #pragma unroll
                for (int ni = 0; ni < 8; ni++)
                    mma_tf32(acc[mi][ni], a[mi], b[ni]);
        }

        if (more) {
            const int nxt = cur ^ 1;
            #pragma unroll
            for (int i = 0; i < 4; i++) {
                uint32_t* da = &As[nxt][(lr + i * 32) * GST + lq];
                uint32_t* dw = &Ws[nxt][(lr + i * 32) * GST + lq];
                da[0] = f2tf32(pa[i].x); da[1] = f2tf32(pa[i].y);
                da[2] = f2tf32(pa[i].z); da[3] = f2tf32(pa[i].w);
                dw[0] = f2tf32(pw[i].x); dw[1] = f2tf32(pw[i].y);
                dw[2] = f2tf32(pw[i].z); dw[3] = f2tf32(pw[i].w);
            }
        }
        __syncthreads();
    }

    #pragma unroll
    for (int mi = 0; mi < 4; mi++) {
        #pragma unroll
        for (int ni = 0; ni < 8; ni++) {
            const int col = n0 + wn + ni * 8 + 2 * t;
            #pragma unroll
            for (int half = 0; half < 2; half++) {
                const int row = m0 + wm + mi * 16 + g + half * 8;
                float2 v;
                v.x = acc[mi][ni][half * 2 + 0];
                v.y = acc[mi][ni][half * 2 + 1];
                if (HEAD_LAYOUT) {
                    const int b = row >> 11;
                    const int s = row & (S_ - 1);
                    const int h = col >> 6;
                    const int d = col & (D_ - 1);
                    *(float2*)(C + ((size_t)(b * H_ + h) * S_ + s) * D_ + d) = v;
                } else {
                    *(float2*)(C + (size_t)row * E_ + col) = v;
                }
            }
        }
    }
}

// ---------------------------------------------------------------------------
// Tensor-core flash attention (unchanged from R5 passing version).
// ---------------------------------------------------------------------------
#define AQT 128
#define AKT 64
#define QST 68
#define KST 68
#define VST 72
#define SQ_WORDS (AQT * QST)
#define SK_WORDS (AKT * KST)
#define SV_WORDS (AKT * VST)
#define ATTN_SMEM ((SQ_WORDS + SK_WORDS + SV_WORDS) * 4)

__global__ __launch_bounds__(256, 2)
void attn_mma_kernel()
{
    extern __shared__ uint32_t dsm[];
    uint32_t* sQ = dsm;
    uint32_t* sK = dsm + SQ_WORDS;
    uint32_t* sV = dsm + SQ_WORDS + SK_WORDS;

    const int tid  = threadIdx.x;
    const int w    = tid >> 5;
    const int lane = tid & 31;
    const int g    = lane >> 2;
    const int t    = lane & 3;
    const int bh   = blockIdx.y;
    const int q0   = blockIdx.x * AQT;
    const int qrow = q0 + w * 16;

    {
        const float4* Qg = (const float4*)(g_q + ((size_t)bh * S_ + q0) * D_);
        #pragma unroll
        for (int i = 0; i < 8; i++) {
            const int idx = tid + i * 256;
            const int r = idx >> 4, c4 = (idx & 15) * 4;
            float4 v = Qg[idx];
            uint32_t* d = &sQ[r * QST + c4];
            d[0] = f2tf32(v.x * QSCALE_); d[1] = f2tf32(v.y * QSCALE_);
            d[2] = f2tf32(v.z * QSCALE_); d[3] = f2tf32(v.w * QSCALE_);
        }
    }

    float oacc[8][4];
    #pragma unroll
    for (int ni = 0; ni < 8; ni++)
        #pragma unroll
        for (int r = 0; r < 4; r++) oacc[ni][r] = 0.0f;

    float mA = -1e30f, mB = -1e30f, lA = 0.0f, lB = 0.0f;

    const float* Kb = g_k + (size_t)bh * S_ * D_;
    const float* Vb = g_v + (size_t)bh * S_ * D_;

    for (int j0 = 0; j0 < S_; j0 += AKT) {
        __syncthreads();
        {
            const float4* Kg = (const float4*)(Kb + (size_t)j0 * D_);
            const float4* Vg = (const float4*)(Vb + (size_t)j0 * D_);
            float4 tk[4], tv[4];
            #pragma unroll
            for (int i = 0; i < 4; i++) { tk[i] = Kg[tid + i * 256]; tv[i] = Vg[tid + i * 256]; }
            #pragma unroll
            for (int i = 0; i < 4; i++) {
                const int idx = tid + i * 256;
                const int r = idx >> 4, c4 = (idx & 15) * 4;
                uint32_t* dk = &sK[r * KST + c4];
                uint32_t* dv = &sV[r * VST + c4];
                dk[0] = f2tf32(tk[i].x); dk[1] = f2tf32(tk[i].y);
                dk[2] = f2tf32(tk[i].z); dk[3] = f2tf32(tk[i].w);
                dv[0] = f2tf32(tv[i].x); dv[1] = f2tf32(tv[i].y);
                dv[2] = f2tf32(tv[i].z); dv[3] = f2tf32(tv[i].w);
            }
        }
        __syncthreads();

        float sc[8][4];
        #pragma unroll
        for (int ni = 0; ni < 8; ni++)
            #pragma unroll
            for (int r = 0; r < 4; r++) sc[ni][r] = 0.0f;

        #pragma unroll
        for (int kc = 0; kc < 8; kc++) {
            uint32_t a[4];
            const int qr = w * 16;
            a[0] = sQ[(qr + g)     * QST + kc * 8 + t];
            a[1] = sQ[(qr + g + 8) * QST + kc * 8 + t];
            a[2] = sQ[(qr + g)     * QST + kc * 8 + t + 4];
            a[3] = sQ[(qr + g + 8) * QST + kc * 8 + t + 4];
            #pragma unroll
            for (int ni = 0; ni < 8; ni++) {
                uint32_t b[2];
                b[0] = sK[(ni * 8 + g) * KST + kc * 8 + t];
                b[1] = sK[(ni * 8 + g) * KST + kc * 8 + t + 4];
                mma_tf32(sc[ni], a, b);
            }
        }

        float rmA = -1e30f, rmB = -1e30f;
        #pragma unroll
        for (int ni = 0; ni < 8; ni++) {
            rmA = fmaxf(rmA, fmaxf(sc[ni][0], sc[ni][1]));
            rmB = fmaxf(rmB, fmaxf(sc[ni][2], sc[ni][3]));
        }
        rmA = fmaxf(rmA, __shfl_xor_sync(0xffffffffu, rmA, 1));
        rmA = fmaxf(rmA, __shfl_xor_sync(0xffffffffu, rmA, 2));
        rmB = fmaxf(rmB, __shfl_xor_sync(0xffffffffu, rmB, 1));
        rmB = fmaxf(rmB, __shfl_xor_sync(0xffffffffu, rmB, 2));

        const float nmA = fmaxf(mA, rmA);
        const float nmB = fmaxf(mB, rmB);
        const float cfA = exp2f(mA - nmA);
        const float cfB = exp2f(mB - nmB);
        mA = nmA; mB = nmB;

        float rsA = 0.0f, rsB = 0.0f;
        #pragma unroll
        for (int ni = 0; ni < 8; ni++) {
            sc[ni][0] = exp2f(sc[ni][0] - mA); rsA += sc[ni][0];
            sc[ni][1] = exp2f(sc[ni][1] - mA); rsA += sc[ni][1];
            sc[ni][2] = exp2f(sc[ni][2] - mB); rsB += sc[ni][2];
            sc[ni][3] = exp2f(sc[ni][3] - mB); rsB += sc[ni][3];
        }
        rsA += __shfl_xor_sync(0xffffffffu, rsA, 1);
        rsA += __shfl_xor_sync(0xffffffffu, rsA, 2);
        rsB += __shfl_xor_sync(0xffffffffu, rsB, 1);
        rsB += __shfl_xor_sync(0xffffffffu, rsB, 2);
        lA = lA * cfA + rsA;
        lB = lB * cfB + rsB;

        #pragma unroll
        for (int ni = 0; ni < 8; ni++) {
            oacc[ni][0] *= cfA; oacc[ni][1] *= cfA;
            oacc[ni][2] *= cfB; oacc[ni][3] *= cfB;
        }

        const int src0 = (lane & ~3) | (t >> 1);
        const int src1 = src0 + 2;
        #pragma unroll
        for (int kc = 0; kc < 8; kc++) {
            const float q00 = __shfl_sync(0xffffffffu, sc[kc][0], src0);
            const float q01 = __shfl_sync(0xffffffffu, sc[kc][1], src0);
            const float q10 = __shfl_sync(0xffffffffu, sc[kc][0], src1);
            const float q11 = __shfl_sync(0xffffffffu, sc[kc][1], src1);
            const float q20 = __shfl_sync(0xffffffffu, sc[kc][2], src0);
            const float q21 = __shfl_sync(0xffffffffu, sc[kc][3], src0);
            const float q30 = __shfl_sync(0xffffffffu, sc[kc][2], src1);
            const float q31 = __shfl_sync(0xffffffffu, sc[kc][3], src1);
            uint32_t ap[4];
            ap[0] = f2tf32((t & 1) ? q01 : q00);
            ap[2] = f2tf32((t & 1) ? q11 : q10);
            ap[1] = f2tf32((t & 1) ? q21 : q20);
            ap[3] = f2tf32((t & 1) ? q31 : q30);
            #pragma unroll
            for (int ni = 0; ni < 8; ni++) {
                uint32_t b[2];
                b[0] = sV[(kc * 8 + t    ) * VST + ni * 8 + g];
                b[1] = sV[(kc * 8 + t + 4) * VST + ni * 8 + g];
                mma_tf32(oacc[ni], ap, b);
            }
        }
    }

    const float ivA = 1.0f / lA;
    const float ivB = 1.0f / lB;
    const int b = bh / H_;
    const int h = bh % H_;
    float* OA = g_att + ((size_t)(b * S_ + qrow + g    ) * E_) + h * D_;
    float* OB = g_att + ((size_t)(b * S_ + qrow + g + 8) * E_) + h * D_;
    #pragma unroll
    for (int ni = 0; ni < 8; ni++) {
        float2 va, vb;
        va.x = oacc[ni][0] * ivA; va.y = oacc[ni][1] * ivA;
        vb.x = oacc[ni][2] * ivB; vb.y = oacc[ni][3] * ivB;
        *(float2*)(OA + ni * 8 + 2 * t) = va;
        *(float2*)(OB + ni * 8 + 2 * t) = vb;
    }
}

// ---------------------------------------------------------------------------
// Launch
// ---------------------------------------------------------------------------
extern "C" void kernel_launch(void* const* d_in, const int* in_sizes, int n_in,
                              void* d_out, int out_size)
{
    (void)in_sizes; (void)n_in; (void)out_size;
    const float* x  = (const float*)d_in[0];
    const float* wq = (const float*)d_in[1];
    const float* wk = (const float*)d_in[2];
    const float* wv = (const float*)d_in[3];
    const float* wo = (const float*)d_in[4];
    float* out = (float*)d_out;

    float *pq, *pk, *pv, *pa;
    cudaGetSymbolAddress((void**)&pq, g_q);
    cudaGetSymbolAddress((void**)&pk, g_k);
    cudaGetSymbolAddress((void**)&pv, g_v);
    cudaGetSymbolAddress((void**)&pa, g_att);

    gemm_tf32_kernel<true><<<dim3(E_ / GN, M_ / GM, 3), 128>>>(
        x, wq, wk, wv, pq, pk, pv);

    cudaFuncSetAttribute(attn_mma_kernel,
                         cudaFuncAttributeMaxDynamicSharedMemorySize, ATTN_SMEM);
    attn_mma_kernel<<<dim3(S_ / AQT, B_ * H_), 256, ATTN_SMEM>>>();

    gemm_tf32_kernel<false><<<dim3(E_ / GN, M_ / GM, 1), 128>>>(
        pa, wo, wo, wo, out, out, out);
}

// round 8
// speedup vs baseline: 7.0131x; 1.4090x over previous
#include <cuda_runtime.h>
#include <math.h>
#include <stdint.h>

#define B_ 2
#define S_ 2048
#define E_ 1024
#define H_ 16
#define D_ 64
#define M_ (B_*S_)
#define QSCALE_ 0.18033688011112042f   // 0.125 * log2(e)

__device__ float g_q[B_*H_*S_*D_];
__device__ float g_k[B_*H_*S_*D_];
__device__ float g_v[B_*H_*S_*D_];
__device__ float g_att[B_*S_*E_];

// ---------------------------------------------------------------------------
// fp16 helpers
// ---------------------------------------------------------------------------
__device__ __forceinline__ uint32_t packh2(float lo, float hi) {
    uint32_t r;
    asm("cvt.rn.f16x2.f32 %0, %1, %2;" : "=r"(r) : "f"(hi), "f"(lo));
    return r;
}

__device__ __forceinline__ void mma_f16(float c[4], const uint32_t a[4],
                                        const uint32_t b[2]) {
    asm volatile(
        "mma.sync.aligned.m16n8k16.row.col.f32.f16.f16.f32 "
        "{%0,%1,%2,%3}, {%4,%5,%6,%7}, {%8,%9}, {%0,%1,%2,%3};"
        : "+f"(c[0]), "+f"(c[1]), "+f"(c[2]), "+f"(c[3])
        : "r"(a[0]), "r"(a[1]), "r"(a[2]), "r"(a[3]), "r"(b[0]), "r"(b[1]));
}

// ---------------------------------------------------------------------------
// fp16 GEMM: C[m][n] = sum_k A[m][k]*W[n][k]   (f32 in, f32 out, f16 MMA)
// Block tile 128x128, BK=32. 128 threads = 4 warps 2x2, warp tile 64x64.
// smem rows: 16 half2 words data + 4 pad (stride 20) -> conflict-free.
// Double buffered, one __syncthreads per k-tile.
// ---------------------------------------------------------------------------
#define GM 128
#define GN 128
#define GK 32
#define GST 20
#define NKT (E_ / GK)

template<bool HEAD_LAYOUT>
__global__ __launch_bounds__(128)
void gemm_f16_kernel(const float* __restrict__ A,
                     const float* __restrict__ W0, const float* __restrict__ W1,
                     const float* __restrict__ W2,
                     float* __restrict__ C0, float* __restrict__ C1,
                     float* __restrict__ C2)
{
    __shared__ uint32_t As[2][GM * GST];
    __shared__ uint32_t Ws[2][GN * GST];

    const float* W = (blockIdx.z == 0) ? W0 : (blockIdx.z == 1) ? W1 : W2;
    float*       C = (blockIdx.z == 0) ? C0 : (blockIdx.z == 1) ? C1 : C2;

    const int tid  = threadIdx.x;
    const int wid  = tid >> 5;
    const int lane = tid & 31;
    const int g    = lane >> 2;
    const int t    = lane & 3;
    const int wm   = (wid & 1) * 64;
    const int wn   = (wid >> 1) * 64;
    const int m0   = blockIdx.y * GM;
    const int n0   = blockIdx.x * GN;

    const int lr = tid >> 2;          // 0..31 base row
    const int lc = tid & 3;           // float8 chunk: floats lc*8..lc*8+7

    float acc[4][8][4];
    #pragma unroll
    for (int mi = 0; mi < 4; mi++)
        #pragma unroll
        for (int ni = 0; ni < 8; ni++)
            #pragma unroll
            for (int r = 0; r < 4; r++) acc[mi][ni][r] = 0.0f;

    const float* Ab = A + (size_t)(m0 + lr) * E_ + lc * 8;
    const float* Wb = W + (size_t)(n0 + lr) * E_ + lc * 8;

    float4 pa[4][2], pw[4][2];
    #pragma unroll
    for (int i = 0; i < 4; i++) {
        pa[i][0] = *(const float4*)(Ab + (size_t)(i * 32) * E_);
        pa[i][1] = *(const float4*)(Ab + (size_t)(i * 32) * E_ + 4);
        pw[i][0] = *(const float4*)(Wb + (size_t)(i * 32) * E_);
        pw[i][1] = *(const float4*)(Wb + (size_t)(i * 32) * E_ + 4);
    }
    // store tile 0 into buffer 0
    #pragma unroll
    for (int i = 0; i < 4; i++) {
        const int base = (lr + i * 32) * GST + lc * 4;
        uint4 va, vw;
        va.x = packh2(pa[i][0].x, pa[i][0].y);
        va.y = packh2(pa[i][0].z, pa[i][0].w);
        va.z = packh2(pa[i][1].x, pa[i][1].y);
        va.w = packh2(pa[i][1].z, pa[i][1].w);
        vw.x = packh2(pw[i][0].x, pw[i][0].y);
        vw.y = packh2(pw[i][0].z, pw[i][0].w);
        vw.z = packh2(pw[i][1].x, pw[i][1].y);
        vw.w = packh2(pw[i][1].z, pw[i][1].w);
        *(uint4*)&As[0][base] = va;
        *(uint4*)&Ws[0][base] = vw;
    }
    __syncthreads();

    for (int kt = 0; kt < NKT; kt++) {
        const int cur = kt & 1;
        const bool more = (kt + 1) < NKT;
        if (more) {
            const int off = (kt + 1) * GK;
            #pragma unroll
            for (int i = 0; i < 4; i++) {
                pa[i][0] = *(const float4*)(Ab + (size_t)(i * 32) * E_ + off);
                pa[i][1] = *(const float4*)(Ab + (size_t)(i * 32) * E_ + off + 4);
                pw[i][0] = *(const float4*)(Wb + (size_t)(i * 32) * E_ + off);
                pw[i][1] = *(const float4*)(Wb + (size_t)(i * 32) * E_ + off + 4);
            }
        }

        #pragma unroll
        for (int ks = 0; ks < 2; ks++) {
            const int kb = ks * 8;
            uint32_t a[4][4];
            #pragma unroll
            for (int mi = 0; mi < 4; mi++) {
                const int mr = wm + mi * 16;
                a[mi][0] = As[cur][(mr + g)     * GST + kb + t];
                a[mi][1] = As[cur][(mr + g + 8) * GST + kb + t];
                a[mi][2] = As[cur][(mr + g)     * GST + kb + t + 4];
                a[mi][3] = As[cur][(mr + g + 8) * GST + kb + t + 4];
            }
            uint32_t b[8][2];
            #pragma unroll
            for (int ni = 0; ni < 8; ni++) {
                const int nc = wn + ni * 8;
                b[ni][0] = Ws[cur][(nc + g) * GST + kb + t];
                b[ni][1] = Ws[cur][(nc + g) * GST + kb + t + 4];
            }
            #pragma unroll
            for (int mi = 0; mi < 4; mi++)
                #pragma unroll
                for (int ni = 0; ni < 8; ni++)
                    mma_f16(acc[mi][ni], a[mi], b[ni]);
        }

        if (more) {
            const int nxt = cur ^ 1;
            #pragma unroll
            for (int i = 0; i < 4; i++) {
                const int base = (lr + i * 32) * GST + lc * 4;
                uint4 va, vw;
                va.x = packh2(pa[i][0].x, pa[i][0].y);
                va.y = packh2(pa[i][0].z, pa[i][0].w);
                va.z = packh2(pa[i][1].x, pa[i][1].y);
                va.w = packh2(pa[i][1].z, pa[i][1].w);
                vw.x = packh2(pw[i][0].x, pw[i][0].y);
                vw.y = packh2(pw[i][0].z, pw[i][0].w);
                vw.z = packh2(pw[i][1].x, pw[i][1].y);
                vw.w = packh2(pw[i][1].z, pw[i][1].w);
                *(uint4*)&As[nxt][base] = va;
                *(uint4*)&Ws[nxt][base] = vw;
            }
        }
        __syncthreads();
    }

    #pragma unroll
    for (int mi = 0; mi < 4; mi++) {
        #pragma unroll
        for (int ni = 0; ni < 8; ni++) {
            const int col = n0 + wn + ni * 8 + 2 * t;
            #pragma unroll
            for (int half = 0; half < 2; half++) {
                const int row = m0 + wm + mi * 16 + g + half * 8;
                float2 v;
                v.x = acc[mi][ni][half * 2 + 0];
                v.y = acc[mi][ni][half * 2 + 1];
                if (HEAD_LAYOUT) {
                    const int b = row >> 11;
                    const int s = row & (S_ - 1);
                    const int h = col >> 6;
                    const int d = col & (D_ - 1);
                    *(float2*)(C + ((size_t)(b * H_ + h) * S_ + s) * D_ + d) = v;
                } else {
                    *(float2*)(C + (size_t)row * E_ + col) = v;
                }
            }
        }
    }
}

// ---------------------------------------------------------------------------
// fp16 tensor-core flash attention.
// Block 128 q-rows, 256 threads (8 warps x 16 rows). KV tile 64 keys.
// sQ/sK: [rows][32 half2 words] stride 36 (banks 4g+t, conflict-free).
// sVT:   V transposed [d][keypair] stride 36 -> PV B-frags pack adjacent keys.
// P->A-fragment remap is pure register packing (no shfl).
// Softmax base-2 (scale*log2e folded into Q).
// ---------------------------------------------------------------------------
#define AQT 128
#define AKT 64
#define AST 36
#define SQ_WORDS (AQT * AST)
#define SK_WORDS (AKT * AST)
#define SV_WORDS (AKT * AST)
#define ATTN_SMEM ((SQ_WORDS + SK_WORDS + SV_WORDS) * 4)

__global__ __launch_bounds__(256, 2)
void attn_f16_kernel()
{
    extern __shared__ uint32_t dsm[];
    uint32_t* sQ  = dsm;
    uint32_t* sK  = dsm + SQ_WORDS;
    uint32_t* sVT = dsm + SQ_WORDS + SK_WORDS;

    const int tid  = threadIdx.x;
    const int w    = tid >> 5;
    const int lane = tid & 31;
    const int g    = lane >> 2;
    const int t    = lane & 3;
    const int bh   = blockIdx.y;
    const int q0   = blockIdx.x * AQT;
    const int qrow = q0 + w * 16;

    // ---- stage Q (128x64), scaled to log2 domain, packed half2 ----
    {
        const float4* Qg = (const float4*)(g_q + ((size_t)bh * S_ + q0) * D_);
        #pragma unroll
        for (int i = 0; i < 8; i++) {
            const int idx = tid + i * 256;
            const int r = idx >> 4, c = idx & 15;
            float4 v = Qg[idx];
            uint2 pkd;
            pkd.x = packh2(v.x * QSCALE_, v.y * QSCALE_);
            pkd.y = packh2(v.z * QSCALE_, v.w * QSCALE_);
            *(uint2*)&sQ[r * AST + c * 2] = pkd;
        }
    }

    float oacc[8][4];
    #pragma unroll
    for (int ni = 0; ni < 8; ni++)
        #pragma unroll
        for (int r = 0; r < 4; r++) oacc[ni][r] = 0.0f;

    float mA = -1e30f, mB = -1e30f, lA = 0.0f, lB = 0.0f;

    const float* Kb = g_k + (size_t)bh * S_ * D_;
    const float* Vb = g_v + (size_t)bh * S_ * D_;

    const int vp = tid & 31;      // keypair 0..31
    const int vq = tid >> 5;      // d-block base 0..7

    for (int j0 = 0; j0 < S_; j0 += AKT) {
        __syncthreads();
        // K: 64 keys x 64 d, row-major packed half2
        {
            const float4* Kg = (const float4*)(Kb + (size_t)j0 * D_);
            #pragma unroll
            for (int i = 0; i < 4; i++) {
                const int idx = tid + i * 256;
                const int r = idx >> 4, c = idx & 15;
                float4 v = Kg[idx];
                uint2 pkd;
                pkd.x = packh2(v.x, v.y);
                pkd.y = packh2(v.z, v.w);
                *(uint2*)&sK[r * AST + c * 2] = pkd;
            }
        }
        // V transposed: sVT[d][keypair], half2 = {V[2p][d], V[2p+1][d]}
        {
            #pragma unroll
            for (int pass = 0; pass < 2; pass++) {
                const int q = vq + pass * 8;          // d-block 0..15
                float4 f0 = *(const float4*)(Vb + (size_t)(j0 + 2 * vp) * D_ + q * 4);
                float4 f1 = *(const float4*)(Vb + (size_t)(j0 + 2 * vp + 1) * D_ + q * 4);
                sVT[(q * 4 + 0) * AST + vp] = packh2(f0.x, f1.x);
                sVT[(q * 4 + 1) * AST + vp] = packh2(f0.y, f1.y);
                sVT[(q * 4 + 2) * AST + vp] = packh2(f0.z, f1.z);
                sVT[(q * 4 + 3) * AST + vp] = packh2(f0.w, f1.w);
            }
        }
        __syncthreads();

        // ---- scores: S = Q K^T (16 x 64 per warp), 4 k16 steps ----
        float sc[8][4];
        #pragma unroll
        for (int ni = 0; ni < 8; ni++)
            #pragma unroll
            for (int r = 0; r < 4; r++) sc[ni][r] = 0.0f;

        #pragma unroll
        for (int kc = 0; kc < 4; kc++) {
            uint32_t a[4];
            a[0] = sQ[(qrow - q0 + g)     * AST + kc * 8 + t];
            a[1] = sQ[(qrow - q0 + g + 8) * AST + kc * 8 + t];
            a[2] = sQ[(qrow - q0 + g)     * AST + kc * 8 + t + 4];
            a[3] = sQ[(qrow - q0 + g + 8) * AST + kc * 8 + t + 4];
            #pragma unroll
            for (int ni = 0; ni < 8; ni++) {
                uint32_t b[2];
                b[0] = sK[(ni * 8 + g) * AST + kc * 8 + t];
                b[1] = sK[(ni * 8 + g) * AST + kc * 8 + t + 4];
                mma_f16(sc[ni], a, b);
            }
        }

        // ---- online softmax (base-2) ----
        float rmA = -1e30f, rmB = -1e30f;
        #pragma unroll
        for (int ni = 0; ni < 8; ni++) {
            rmA = fmaxf(rmA, fmaxf(sc[ni][0], sc[ni][1]));
            rmB = fmaxf(rmB, fmaxf(sc[ni][2], sc[ni][3]));
        }
        rmA = fmaxf(rmA, __shfl_xor_sync(0xffffffffu, rmA, 1));
        rmA = fmaxf(rmA, __shfl_xor_sync(0xffffffffu, rmA, 2));
        rmB = fmaxf(rmB, __shfl_xor_sync(0xffffffffu, rmB, 1));
        rmB = fmaxf(rmB, __shfl_xor_sync(0xffffffffu, rmB, 2));

        const float nmA = fmaxf(mA, rmA);
        const float nmB = fmaxf(mB, rmB);
        const float cfA = exp2f(mA - nmA);
        const float cfB = exp2f(mB - nmB);
        mA = nmA; mB = nmB;

        float rsA = 0.0f, rsB = 0.0f;
        #pragma unroll
        for (int ni = 0; ni < 8; ni++) {
            sc[ni][0] = exp2f(sc[ni][0] - mA); rsA += sc[ni][0];
            sc[ni][1] = exp2f(sc[ni][1] - mA); rsA += sc[ni][1];
            sc[ni][2] = exp2f(sc[ni][2] - mB); rsB += sc[ni][2];
            sc[ni][3] = exp2f(sc[ni][3] - mB); rsB += sc[ni][3];
        }
        rsA += __shfl_xor_sync(0xffffffffu, rsA, 1);
        rsA += __shfl_xor_sync(0xffffffffu, rsA, 2);
        rsB += __shfl_xor_sync(0xffffffffu, rsB, 1);
        rsB += __shfl_xor_sync(0xffffffffu, rsB, 2);
        lA = lA * cfA + rsA;
        lB = lB * cfB + rsB;

        #pragma unroll
        for (int ni = 0; ni < 8; ni++) {
            oacc[ni][0] *= cfA; oacc[ni][1] *= cfA;
            oacc[ni][2] *= cfB; oacc[ni][3] *= cfB;
        }

        // ---- O += P V : A-frag = packed score accumulators (no shfl) ----
        #pragma unroll
        for (int kc = 0; kc < 4; kc++) {
            uint32_t ap[4];
            ap[0] = packh2(sc[2 * kc][0],     sc[2 * kc][1]);
            ap[1] = packh2(sc[2 * kc][2],     sc[2 * kc][3]);
            ap[2] = packh2(sc[2 * kc + 1][0], sc[2 * kc + 1][1]);
            ap[3] = packh2(sc[2 * kc + 1][2], sc[2 * kc + 1][3]);
            #pragma unroll
            for (int ni = 0; ni < 8; ni++) {
                uint32_t b[2];
                b[0] = sVT[(ni * 8 + g) * AST + kc * 8 + t];
                b[1] = sVT[(ni * 8 + g) * AST + kc * 8 + t + 4];
                mma_f16(oacc[ni], ap, b);
            }
        }
    }

    // ---- epilogue: normalize, write merged-head [B,S,E] ----
    const float ivA = 1.0f / lA;
    const float ivB = 1.0f / lB;
    const int b = bh / H_;
    const int h = bh % H_;
    float* OA = g_att + ((size_t)(b * S_ + qrow + g    ) * E_) + h * D_;
    float* OB = g_att + ((size_t)(b * S_ + qrow + g + 8) * E_) + h * D_;
    #pragma unroll
    for (int ni = 0; ni < 8; ni++) {
        float2 va, vb;
        va.x = oacc[ni][0] * ivA; va.y = oacc[ni][1] * ivA;
        vb.x = oacc[ni][2] * ivB; vb.y = oacc[ni][3] * ivB;
        *(float2*)(OA + ni * 8 + 2 * t) = va;
        *(float2*)(OB + ni * 8 + 2 * t) = vb;
    }
}

// ---------------------------------------------------------------------------
// Launch
// ---------------------------------------------------------------------------
extern "C" void kernel_launch(void* const* d_in, const int* in_sizes, int n_in,
                              void* d_out, int out_size)
{
    (void)in_sizes; (void)n_in; (void)out_size;
    const float* x  = (const float*)d_in[0];
    const float* wq = (const float*)d_in[1];
    const float* wk = (const float*)d_in[2];
    const float* wv = (const float*)d_in[3];
    const float* wo = (const float*)d_in[4];
    float* out = (float*)d_out;

    float *pq, *pk, *pv, *pa;
    cudaGetSymbolAddress((void**)&pq, g_q);
    cudaGetSymbolAddress((void**)&pk, g_k);
    cudaGetSymbolAddress((void**)&pv, g_v);
    cudaGetSymbolAddress((void**)&pa, g_att);

    gemm_f16_kernel<true><<<dim3(E_ / GN, M_ / GM, 3), 128>>>(
        x, wq, wk, wv, pq, pk, pv);

    cudaFuncSetAttribute(attn_f16_kernel,
                         cudaFuncAttributeMaxDynamicSharedMemorySize, ATTN_SMEM);
    attn_f16_kernel<<<dim3(S_ / AQT, B_ * H_), 256, ATTN_SMEM>>>();

    gemm_f16_kernel<false><<<dim3(E_ / GN, M_ / GM, 1), 128>>>(
        pa, wo, wo, wo, out, out, out);
}

// round 9
// speedup vs baseline: 8.5997x; 1.2262x over previous
#include <cuda_runtime.h>
#include <cuda_fp16.h>
#include <math.h>
#include <stdint.h>

#define B_ 2
#define S_ 2048
#define E_ 1024
#define H_ 16
#define D_ 64
#define M_ (B_*S_)
#define QSCALE_ 0.18033688011112042f   // 0.125 * log2(e)

// fp16 intermediates
__device__ __half g_q[B_*H_*S_*D_];
__device__ __half g_k[B_*H_*S_*D_];
__device__ __half g_v[B_*H_*S_*D_];
__device__ __half g_att[B_*S_*E_];

// ---------------------------------------------------------------------------
// helpers
// ---------------------------------------------------------------------------
__device__ __forceinline__ uint32_t packh2(float lo, float hi) {
    uint32_t r;
    asm("cvt.rn.f16x2.f32 %0, %1, %2;" : "=r"(r) : "f"(hi), "f"(lo));
    return r;
}

__device__ __forceinline__ void mma_f16(float c[4], const uint32_t a[4],
                                        uint32_t b0, uint32_t b1) {
    asm volatile(
        "mma.sync.aligned.m16n8k16.row.col.f32.f16.f16.f32 "
        "{%0,%1,%2,%3}, {%4,%5,%6,%7}, {%8,%9}, {%0,%1,%2,%3};"
        : "+f"(c[0]), "+f"(c[1]), "+f"(c[2]), "+f"(c[3])
        : "r"(a[0]), "r"(a[1]), "r"(a[2]), "r"(a[3]), "r"(b0), "r"(b1));
}

__device__ __forceinline__ void ldsm_x4(uint32_t& r0, uint32_t& r1,
                                        uint32_t& r2, uint32_t& r3,
                                        uint32_t addr) {
    asm volatile("ldmatrix.sync.aligned.m8n8.x4.shared.b16 {%0,%1,%2,%3}, [%4];"
                 : "=r"(r0), "=r"(r1), "=r"(r2), "=r"(r3) : "r"(addr));
}

__device__ __forceinline__ uint32_t s2u(const void* p) {
    uint32_t a;
    asm("{ .reg .u64 t; cvta.to.shared.u64 t, %1; cvt.u32.u64 %0, t; }"
        : "=r"(a) : "l"(p));
    return a;
}

__device__ __forceinline__ uint32_t prmt(uint32_t a, uint32_t b, uint32_t sel) {
    uint32_t r;
    asm("prmt.b32 %0, %1, %2, %3;" : "=r"(r) : "r"(a), "r"(b), "r"(sel));
    return r;
}

// ---------------------------------------------------------------------------
// QKV GEMM: A fp32 [M,E], W fp32 [N,E] -> C fp16 head layout [B,H,S,D]
// Block 128x128, BK=32 halves. 4 warps 2x2, warp tile 64x64.
// smem stride 20 words; fragments via ldmatrix.x4 (conflict-free).
// ---------------------------------------------------------------------------
#define GM 128
#define GN 128
#define GK 32
#define GST 20
#define NKT (E_ / GK)
#define BUFW (GM * GST)

__global__ __launch_bounds__(128)
void gemm_qkv_kernel(const float* __restrict__ A,
                     const float* __restrict__ W0, const float* __restrict__ W1,
                     const float* __restrict__ W2,
                     __half* __restrict__ C0, __half* __restrict__ C1,
                     __half* __restrict__ C2)
{
    __shared__ uint32_t As[2][BUFW];
    __shared__ uint32_t Ws[2][BUFW];

    const float* W = (blockIdx.z == 0) ? W0 : (blockIdx.z == 1) ? W1 : W2;
    __half*     C = (blockIdx.z == 0) ? C0 : (blockIdx.z == 1) ? C1 : C2;
    const float oscale = (blockIdx.z == 0) ? QSCALE_ : 1.0f;

    const int tid  = threadIdx.x;
    const int wid  = tid >> 5;
    const int lane = tid & 31;
    const int g    = lane >> 2;
    const int t    = lane & 3;
    const int wm   = (wid & 1) * 64;
    const int wn   = (wid >> 1) * 64;
    const int m0   = blockIdx.y * GM;
    const int n0   = blockIdx.x * GN;

    const int lr = tid >> 2;
    const int lc = tid & 3;

    float acc[4][8][4];
    #pragma unroll
    for (int mi = 0; mi < 4; mi++)
        #pragma unroll
        for (int ni = 0; ni < 8; ni++)
            #pragma unroll
            for (int r = 0; r < 4; r++) acc[mi][ni][r] = 0.0f;

    const float* Ab = A + (size_t)(m0 + lr) * E_ + lc * 8;
    const float* Wb = W + (size_t)(n0 + lr) * E_ + lc * 8;

    // ldmatrix lane offsets (bytes within buffer)
    const uint32_t baseA = s2u(&As[0][0]);
    const uint32_t baseW = s2u(&Ws[0][0]);
    const uint32_t aoff = (((lane & 15) * GST) + ((lane >> 4) * 4)) * 4u;
    const uint32_t boff = ((((lane >> 4) * 8 + (lane & 7)) * GST)
                          + (((lane >> 3) & 1) * 4)) * 4u;

    float4 pa[4][2], pw[4][2];
    #pragma unroll
    for (int i = 0; i < 4; i++) {
        pa[i][0] = *(const float4*)(Ab + (size_t)(i * 32) * E_);
        pa[i][1] = *(const float4*)(Ab + (size_t)(i * 32) * E_ + 4);
        pw[i][0] = *(const float4*)(Wb + (size_t)(i * 32) * E_);
        pw[i][1] = *(const float4*)(Wb + (size_t)(i * 32) * E_ + 4);
    }
    #pragma unroll
    for (int i = 0; i < 4; i++) {
        const int base = (lr + i * 32) * GST + lc * 4;
        uint4 va, vw;
        va.x = packh2(pa[i][0].x, pa[i][0].y);
        va.y = packh2(pa[i][0].z, pa[i][0].w);
        va.z = packh2(pa[i][1].x, pa[i][1].y);
        va.w = packh2(pa[i][1].z, pa[i][1].w);
        vw.x = packh2(pw[i][0].x, pw[i][0].y);
        vw.y = packh2(pw[i][0].z, pw[i][0].w);
        vw.z = packh2(pw[i][1].x, pw[i][1].y);
        vw.w = packh2(pw[i][1].z, pw[i][1].w);
        *(uint4*)&As[0][base] = va;
        *(uint4*)&Ws[0][base] = vw;
    }
    __syncthreads();

    for (int kt = 0; kt < NKT; kt++) {
        const int cur = kt & 1;
        const bool more = (kt + 1) < NKT;
        if (more) {
            const int off = (kt + 1) * GK;
            #pragma unroll
            for (int i = 0; i < 4; i++) {
                pa[i][0] = *(const float4*)(Ab + (size_t)(i * 32) * E_ + off);
                pa[i][1] = *(const float4*)(Ab + (size_t)(i * 32) * E_ + off + 4);
                pw[i][0] = *(const float4*)(Wb + (size_t)(i * 32) * E_ + off);
                pw[i][1] = *(const float4*)(Wb + (size_t)(i * 32) * E_ + off + 4);
            }
        }

        const uint32_t bufA = baseA + cur * (BUFW * 4u);
        const uint32_t bufW = baseW + cur * (BUFW * 4u);
        #pragma unroll
        for (int ks = 0; ks < 2; ks++) {
            const uint32_t kb = ks * 32u;   // bytes: 8 words
            uint32_t a[4][4];
            #pragma unroll
            for (int mi = 0; mi < 4; mi++)
                ldsm_x4(a[mi][0], a[mi][1], a[mi][2], a[mi][3],
                        bufA + aoff + (uint32_t)((wm + mi * 16) * GST) * 4u + kb);
            uint32_t b[8][2];
            #pragma unroll
            for (int pr = 0; pr < 4; pr++)
                ldsm_x4(b[2*pr][0], b[2*pr][1], b[2*pr+1][0], b[2*pr+1][1],
                        bufW + boff + (uint32_t)((wn + pr * 16) * GST) * 4u + kb);
            #pragma unroll
            for (int mi = 0; mi < 4; mi++)
                #pragma unroll
                for (int ni = 0; ni < 8; ni++)
                    mma_f16(acc[mi][ni], a[mi], b[ni][0], b[ni][1]);
        }

        if (more) {
            const int nxt = cur ^ 1;
            #pragma unroll
            for (int i = 0; i < 4; i++) {
                const int base = (lr + i * 32) * GST + lc * 4;
                uint4 va, vw;
                va.x = packh2(pa[i][0].x, pa[i][0].y);
                va.y = packh2(pa[i][0].z, pa[i][0].w);
                va.z = packh2(pa[i][1].x, pa[i][1].y);
                va.w = packh2(pa[i][1].z, pa[i][1].w);
                vw.x = packh2(pw[i][0].x, pw[i][0].y);
                vw.y = packh2(pw[i][0].z, pw[i][0].w);
                vw.z = packh2(pw[i][1].x, pw[i][1].y);
                vw.w = packh2(pw[i][1].z, pw[i][1].w);
                *(uint4*)&As[nxt][base] = va;
                *(uint4*)&Ws[nxt][base] = vw;
            }
        }
        __syncthreads();
    }

    // epilogue: fp16 head layout [B,H,S,D], pre-scaled (Q only)
    #pragma unroll
    for (int mi = 0; mi < 4; mi++) {
        #pragma unroll
        for (int ni = 0; ni < 8; ni++) {
            const int col = n0 + wn + ni * 8 + 2 * t;
            const int h = col >> 6;
            const int d = col & (D_ - 1);
            #pragma unroll
            for (int half = 0; half < 2; half++) {
                const int row = m0 + wm + mi * 16 + g + half * 8;
                const int b = row >> 11;
                const int s = row & (S_ - 1);
                uint32_t hv = packh2(acc[mi][ni][half*2+0] * oscale,
                                     acc[mi][ni][half*2+1] * oscale);
                *(uint32_t*)(C + ((size_t)(b * H_ + h) * S_ + s) * D_ + d) = hv;
            }
        }
    }
}

// ---------------------------------------------------------------------------
// Output GEMM: A fp16 [M,E] (g_att), W fp32 [N,E] -> C fp32 [M,N]
// ---------------------------------------------------------------------------
__global__ __launch_bounds__(128)
void gemm_out_kernel(const __half* __restrict__ A, const float* __restrict__ W,
                     float* __restrict__ C)
{
    __shared__ uint32_t As[2][BUFW];
    __shared__ uint32_t Ws[2][BUFW];

    const int tid  = threadIdx.x;
    const int wid  = tid >> 5;
    const int lane = tid & 31;
    const int g    = lane >> 2;
    const int t    = lane & 3;
    const int wm   = (wid & 1) * 64;
    const int wn   = (wid >> 1) * 64;
    const int m0   = blockIdx.y * GM;
    const int n0   = blockIdx.x * GN;

    const int lr = tid >> 2;
    const int lc = tid & 3;

    float acc[4][8][4];
    #pragma unroll
    for (int mi = 0; mi < 4; mi++)
        #pragma unroll
        for (int ni = 0; ni < 8; ni++)
            #pragma unroll
            for (int r = 0; r < 4; r++) acc[mi][ni][r] = 0.0f;

    const __half* Ab = A + (size_t)(m0 + lr) * E_ + lc * 8;
    const float*  Wb = W + (size_t)(n0 + lr) * E_ + lc * 8;

    const uint32_t baseA = s2u(&As[0][0]);
    const uint32_t baseW = s2u(&Ws[0][0]);
    const uint32_t aoff = (((lane & 15) * GST) + ((lane >> 4) * 4)) * 4u;
    const uint32_t boff = ((((lane >> 4) * 8 + (lane & 7)) * GST)
                          + (((lane >> 3) & 1) * 4)) * 4u;

    uint4 pa[4];
    float4 pw[4][2];
    #pragma unroll
    for (int i = 0; i < 4; i++) {
        pa[i] = *(const uint4*)(Ab + (size_t)(i * 32) * E_);
        pw[i][0] = *(const float4*)(Wb + (size_t)(i * 32) * E_);
        pw[i][1] = *(const float4*)(Wb + (size_t)(i * 32) * E_ + 4);
    }
    #pragma unroll
    for (int i = 0; i < 4; i++) {
        const int base = (lr + i * 32) * GST + lc * 4;
        uint4 vw;
        vw.x = packh2(pw[i][0].x, pw[i][0].y);
        vw.y = packh2(pw[i][0].z, pw[i][0].w);
        vw.z = packh2(pw[i][1].x, pw[i][1].y);
        vw.w = packh2(pw[i][1].z, pw[i][1].w);
        *(uint4*)&As[0][base] = pa[i];
        *(uint4*)&Ws[0][base] = vw;
    }
    __syncthreads();

    for (int kt = 0; kt < NKT; kt++) {
        const int cur = kt & 1;
        const bool more = (kt + 1) < NKT;
        if (more) {
            const int off = (kt + 1) * GK;
            #pragma unroll
            for (int i = 0; i < 4; i++) {
                pa[i] = *(const uint4*)(Ab + (size_t)(i * 32) * E_ + off);
                pw[i][0] = *(const float4*)(Wb + (size_t)(i * 32) * E_ + off);
                pw[i][1] = *(const float4*)(Wb + (size_t)(i * 32) * E_ + off + 4);
            }
        }

        const uint32_t bufA = baseA + cur * (BUFW * 4u);
        const uint32_t bufW = baseW + cur * (BUFW * 4u);
        #pragma unroll
        for (int ks = 0; ks < 2; ks++) {
            const uint32_t kb = ks * 32u;
            uint32_t a[4][4];
            #pragma unroll
            for (int mi = 0; mi < 4; mi++)
                ldsm_x4(a[mi][0], a[mi][1], a[mi][2], a[mi][3],
                        bufA + aoff + (uint32_t)((wm + mi * 16) * GST) * 4u + kb);
            uint32_t b[8][2];
            #pragma unroll
            for (int pr = 0; pr < 4; pr++)
                ldsm_x4(b[2*pr][0], b[2*pr][1], b[2*pr+1][0], b[2*pr+1][1],
                        bufW + boff + (uint32_t)((wn + pr * 16) * GST) * 4u + kb);
            #pragma unroll
            for (int mi = 0; mi < 4; mi++)
                #pragma unroll
                for (int ni = 0; ni < 8; ni++)
                    mma_f16(acc[mi][ni], a[mi], b[ni][0], b[ni][1]);
        }

        if (more) {
            const int nxt = cur ^ 1;
            #pragma unroll
            for (int i = 0; i < 4; i++) {
                const int base = (lr + i * 32) * GST + lc * 4;
                uint4 vw;
                vw.x = packh2(pw[i][0].x, pw[i][0].y);
                vw.y = packh2(pw[i][0].z, pw[i][0].w);
                vw.z = packh2(pw[i][1].x, pw[i][1].y);
                vw.w = packh2(pw[i][1].z, pw[i][1].w);
                *(uint4*)&As[nxt][base] = pa[i];
                *(uint4*)&Ws[nxt][base] = vw;
            }
        }
        __syncthreads();
    }

    #pragma unroll
    for (int mi = 0; mi < 4; mi++) {
        #pragma unroll
        for (int ni = 0; ni < 8; ni++) {
            const int col = n0 + wn + ni * 8 + 2 * t;
            #pragma unroll
            for (int half = 0; half < 2; half++) {
                const int row = m0 + wm + mi * 16 + g + half * 8;
                float2 v;
                v.x = acc[mi][ni][half * 2 + 0];
                v.y = acc[mi][ni][half * 2 + 1];
                *(float2*)(C + (size_t)row * E_ + col) = v;
            }
        }
    }
}

// ---------------------------------------------------------------------------
// fp16 flash attention: all inputs fp16 in gmem (pre-scaled Q).
// Block 128 q-rows, 256 threads. KV tile 64 keys. smem stride 36 words.
// Fragments via ldmatrix.x4. V transposed at staging via prmt.
// ---------------------------------------------------------------------------
#define AQT 128
#define AKT 64
#define AST 36
#define SQ_WORDS (AQT * AST)
#define SK_WORDS (AKT * AST)
#define SV_WORDS (AKT * AST)
#define ATTN_SMEM ((SQ_WORDS + SK_WORDS + SV_WORDS) * 4)

__global__ __launch_bounds__(256, 2)
void attn_f16_kernel()
{
    extern __shared__ uint32_t dsm[];
    uint32_t* sQ  = dsm;
    uint32_t* sK  = dsm + SQ_WORDS;
    uint32_t* sVT = dsm + SQ_WORDS + SK_WORDS;

    const int tid  = threadIdx.x;
    const int w    = tid >> 5;
    const int lane = tid & 31;
    const int g    = lane >> 2;
    const int t    = lane & 3;
    const int bh   = blockIdx.y;
    const int q0   = blockIdx.x * AQT;
    const int qrow = q0 + w * 16;

    const uint32_t baseQ  = s2u(sQ);
    const uint32_t baseK  = s2u(sK);
    const uint32_t baseVT = s2u(sVT);
    const uint32_t aoffQ = (((w * 16 + (lane & 15)) * AST) + ((lane >> 4) * 4)) * 4u;
    const uint32_t boffB = ((((lane >> 4) * 8 + (lane & 7)) * AST)
                           + (((lane >> 3) & 1) * 4)) * 4u;

    // ---- stage Q tile: direct fp16 copies (pre-scaled in GEMM epilogue) ----
    {
        const uint4* Qg = (const uint4*)(g_q + ((size_t)bh * S_ + q0) * D_);
        #pragma unroll
        for (int i = 0; i < 4; i++) {
            const int idx = tid + i * 256;          // 0..1023
            const int r = idx >> 3, c = idx & 7;
            *(uint4*)&sQ[r * AST + c * 4] = Qg[idx];
        }
    }

    float oacc[8][4];
    #pragma unroll
    for (int ni = 0; ni < 8; ni++)
        #pragma unroll
        for (int r = 0; r < 4; r++) oacc[ni][r] = 0.0f;

    float mA = -1e30f, mB = -1e30f, lA = 0.0f, lB = 0.0f;

    const __half* Kb = g_k + (size_t)bh * S_ * D_;
    const __half* Vb = g_v + (size_t)bh * S_ * D_;

    const int vp = tid & 31;     // keypair 0..31
    const int vq = tid >> 5;     // d-chunk 0..7 (8 d each)

    for (int j0 = 0; j0 < S_; j0 += AKT) {
        __syncthreads();
        // K: 64 rows x 8 uint4, direct copy
        {
            const uint4* Kg = (const uint4*)(Kb + (size_t)j0 * D_);
            #pragma unroll
            for (int i = 0; i < 2; i++) {
                const int idx = tid + i * 256;       // 0..511
                const int r = idx >> 3, c = idx & 7;
                *(uint4*)&sK[r * AST + c * 4] = Kg[idx];
            }
        }
        // VT[d][keypair]: prmt interleave of two adjacent key rows
        {
            const uint4 va = *(const uint4*)(Vb + (size_t)(j0 + 2 * vp) * D_ + vq * 8);
            const uint4 vb = *(const uint4*)(Vb + (size_t)(j0 + 2 * vp + 1) * D_ + vq * 8);
            const int db = vq * 8;
            sVT[(db + 0) * AST + vp] = prmt(va.x, vb.x, 0x5410);
            sVT[(db + 1) * AST + vp] = prmt(va.x, vb.x, 0x7632);
            sVT[(db + 2) * AST + vp] = prmt(va.y, vb.y, 0x5410);
            sVT[(db + 3) * AST + vp] = prmt(va.y, vb.y, 0x7632);
            sVT[(db + 4) * AST + vp] = prmt(va.z, vb.z, 0x5410);
            sVT[(db + 5) * AST + vp] = prmt(va.z, vb.z, 0x7632);
            sVT[(db + 6) * AST + vp] = prmt(va.w, vb.w, 0x5410);
            sVT[(db + 7) * AST + vp] = prmt(va.w, vb.w, 0x7632);
        }
        __syncthreads();

        // ---- scores: S = Q K^T (16 x 64 per warp), 4 k16 steps ----
        float sc[8][4];
        #pragma unroll
        for (int ni = 0; ni < 8; ni++)
            #pragma unroll
            for (int r = 0; r < 4; r++) sc[ni][r] = 0.0f;

        #pragma unroll
        for (int kc = 0; kc < 4; kc++) {
            const uint32_t kb = kc * 32u;
            uint32_t a[4];
            ldsm_x4(a[0], a[1], a[2], a[3], baseQ + aoffQ + kb);
            #pragma unroll
            for (int pr = 0; pr < 4; pr++) {
                uint32_t b0, b1, b2, b3;
                ldsm_x4(b0, b1, b2, b3,
                        baseK + boffB + (uint32_t)(pr * 16 * AST) * 4u + kb);
                mma_f16(sc[2*pr],     a, b0, b1);
                mma_f16(sc[2*pr + 1], a, b2, b3);
            }
        }

        // ---- online softmax (base-2) ----
        float rmA = -1e30f, rmB = -1e30f;
        #pragma unroll
        for (int ni = 0; ni < 8; ni++) {
            rmA = fmaxf(rmA, fmaxf(sc[ni][0], sc[ni][1]));
            rmB = fmaxf(rmB, fmaxf(sc[ni][2], sc[ni][3]));
        }
        rmA = fmaxf(rmA, __shfl_xor_sync(0xffffffffu, rmA, 1));
        rmA = fmaxf(rmA, __shfl_xor_sync(0xffffffffu, rmA, 2));
        rmB = fmaxf(rmB, __shfl_xor_sync(0xffffffffu, rmB, 1));
        rmB = fmaxf(rmB, __shfl_xor_sync(0xffffffffu, rmB, 2));

        const float nmA = fmaxf(mA, rmA);
        const float nmB = fmaxf(mB, rmB);
        const float cfA = exp2f(mA - nmA);
        const float cfB = exp2f(mB - nmB);
        mA = nmA; mB = nmB;

        float rsA = 0.0f, rsB = 0.0f;
        #pragma unroll
        for (int ni = 0; ni < 8; ni++) {
            sc[ni][0] = exp2f(sc[ni][0] - mA); rsA += sc[ni][0];
            sc[ni][1] = exp2f(sc[ni][1] - mA); rsA += sc[ni][1];
            sc[ni][2] = exp2f(sc[ni][2] - mB); rsB += sc[ni][2];
            sc[ni][3] = exp2f(sc[ni][3] - mB); rsB += sc[ni][3];
        }
        rsA += __shfl_xor_sync(0xffffffffu, rsA, 1);
        rsA += __shfl_xor_sync(0xffffffffu, rsA, 2);
        rsB += __shfl_xor_sync(0xffffffffu, rsB, 1);
        rsB += __shfl_xor_sync(0xffffffffu, rsB, 2);
        lA = lA * cfA + rsA;
        lB = lB * cfB + rsB;

        #pragma unroll
        for (int ni = 0; ni < 8; ni++) {
            oacc[ni][0] *= cfA; oacc[ni][1] *= cfA;
            oacc[ni][2] *= cfB; oacc[ni][3] *= cfB;
        }

        // ---- O += P V : A-frag = packed score accumulators ----
        #pragma unroll
        for (int kc = 0; kc < 4; kc++) {
            uint32_t ap[4];
            ap[0] = packh2(sc[2 * kc][0],     sc[2 * kc][1]);
            ap[1] = packh2(sc[2 * kc][2],     sc[2 * kc][3]);
            ap[2] = packh2(sc[2 * kc + 1][0], sc[2 * kc + 1][1]);
            ap[3] = packh2(sc[2 * kc + 1][2], sc[2 * kc + 1][3]);
            const uint32_t kb = kc * 32u;
            #pragma unroll
            for (int pr = 0; pr < 4; pr++) {
                uint32_t b0, b1, b2, b3;
                ldsm_x4(b0, b1, b2, b3,
                        baseVT + boffB + (uint32_t)(pr * 16 * AST) * 4u + kb);
                mma_f16(oacc[2*pr],     ap, b0, b1);
                mma_f16(oacc[2*pr + 1], ap, b2, b3);
            }
        }
    }

    // ---- epilogue: normalize, write fp16 merged-head [B,S,E] ----
    const float ivA = 1.0f / lA;
    const float ivB = 1.0f / lB;
    const int b = bh / H_;
    const int h = bh % H_;
    __half* OA = g_att + ((size_t)(b * S_ + qrow + g    ) * E_) + h * D_;
    __half* OB = g_att + ((size_t)(b * S_ + qrow + g + 8) * E_) + h * D_;
    #pragma unroll
    for (int ni = 0; ni < 8; ni++) {
        *(uint32_t*)(OA + ni * 8 + 2 * t) = packh2(oacc[ni][0] * ivA, oacc[ni][1] * ivA);
        *(uint32_t*)(OB + ni * 8 + 2 * t) = packh2(oacc[ni][2] * ivB, oacc[ni][3] * ivB);
    }
}

// ---------------------------------------------------------------------------
// Launch
// ---------------------------------------------------------------------------
extern "C" void kernel_launch(void* const* d_in, const int* in_sizes, int n_in,
                              void* d_out, int out_size)
{
    (void)in_sizes; (void)n_in; (void)out_size;
    const float* x  = (const float*)d_in[0];
    const float* wq = (const float*)d_in[1];
    const float* wk = (const float*)d_in[2];
    const float* wv = (const float*)d_in[3];
    const float* wo = (const float*)d_in[4];
    float* out = (float*)d_out;

    __half *pq, *pk, *pv, *pa;
    cudaGetSymbolAddress((void**)&pq, g_q);
    cudaGetSymbolAddress((void**)&pk, g_k);
    cudaGetSymbolAddress((void**)&pv, g_v);
    cudaGetSymbolAddress((void**)&pa, g_att);

    gemm_qkv_kernel<<<dim3(E_ / GN, M_ / GM, 3), 128>>>(
        x, wq, wk, wv, pq, pk, pv);

    cudaFuncSetAttribute(attn_f16_kernel,
                         cudaFuncAttributeMaxDynamicSharedMemorySize, ATTN_SMEM);
    attn_f16_kernel<<<dim3(S_ / AQT, B_ * H_), 256, ATTN_SMEM>>>();

    gemm_out_kernel<<<dim3(E_ / GN, M_ / GM, 1), 128>>>(pa, wo, out);
}

// round 10
// speedup vs baseline: 9.1642x; 1.0656x over previous
#include <cuda_runtime.h>
#include <cuda_fp16.h>
#include <math.h>
#include <stdint.h>

#define B_ 2
#define S_ 2048
#define E_ 1024
#define H_ 16
#define D_ 64
#define M_ (B_*S_)
#define QSCALE_ 0.18033688011112042f   // 0.125 * log2(e)

// fp16 operand / intermediate buffers
__device__ __half g_x [M_*E_];
__device__ __half g_wq[E_*E_];
__device__ __half g_wk[E_*E_];
__device__ __half g_wv[E_*E_];
__device__ __half g_wo[E_*E_];
__device__ __half g_q[B_*H_*S_*D_];
__device__ __half g_k[B_*H_*S_*D_];
__device__ __half g_v[B_*H_*S_*D_];
__device__ __half g_att[B_*S_*E_];

// ---------------------------------------------------------------------------
// helpers
// ---------------------------------------------------------------------------
__device__ __forceinline__ uint32_t packh2(float lo, float hi) {
    uint32_t r;
    asm("cvt.rn.f16x2.f32 %0, %1, %2;" : "=r"(r) : "f"(hi), "f"(lo));
    return r;
}

__device__ __forceinline__ void mma_f16(float c[4], const uint32_t a[4],
                                        uint32_t b0, uint32_t b1) {
    asm volatile(
        "mma.sync.aligned.m16n8k16.row.col.f32.f16.f16.f32 "
        "{%0,%1,%2,%3}, {%4,%5,%6,%7}, {%8,%9}, {%0,%1,%2,%3};"
        : "+f"(c[0]), "+f"(c[1]), "+f"(c[2]), "+f"(c[3])
        : "r"(a[0]), "r"(a[1]), "r"(a[2]), "r"(a[3]), "r"(b0), "r"(b1));
}

__device__ __forceinline__ void ldsm_x4(uint32_t& r0, uint32_t& r1,
                                        uint32_t& r2, uint32_t& r3,
                                        uint32_t addr) {
    asm volatile("ldmatrix.sync.aligned.m8n8.x4.shared.b16 {%0,%1,%2,%3}, [%4];"
                 : "=r"(r0), "=r"(r1), "=r"(r2), "=r"(r3) : "r"(addr));
}

__device__ __forceinline__ uint32_t s2u(const void* p) {
    uint32_t a;
    asm("{ .reg .u64 t; cvta.to.shared.u64 t, %1; cvt.u32.u64 %0, t; }"
        : "=r"(a) : "l"(p));
    return a;
}

__device__ __forceinline__ uint32_t prmt(uint32_t a, uint32_t b, uint32_t sel) {
    uint32_t r;
    asm("prmt.b32 %0, %1, %2, %3;" : "=r"(r) : "r"(a), "r"(b), "r"(sel));
    return r;
}

__device__ __forceinline__ void cp16(uint32_t smem, const void* g) {
    asm volatile("cp.async.ca.shared.global [%0], [%1], 16;"
                 :: "r"(smem), "l"(g) : "memory");
}
#define CP_COMMIT() asm volatile("cp.async.commit_group;" ::: "memory")
#define CP_WAIT1()  asm volatile("cp.async.wait_group 1;" ::: "memory")
#define CP_WAIT0()  asm volatile("cp.async.wait_group 0;" ::: "memory")

// ---------------------------------------------------------------------------
// f32 -> f16 conversion (elementwise, float4 granularity)
// ---------------------------------------------------------------------------
__global__ void f2h_kernel(const float* __restrict__ src, __half* __restrict__ dst,
                           int n4)
{
    int i = blockIdx.x * blockDim.x + threadIdx.x;
    if (i < n4) {
        float4 v = ((const float4*)src)[i];
        uint2 o;
        o.x = packh2(v.x, v.y);
        o.y = packh2(v.z, v.w);
        ((uint2*)dst)[i] = o;
    }
}

// ---------------------------------------------------------------------------
// fp16 GEMM with cp.async: C[m][n] = sum_k A[m][k]*W[n][k]
// Block 128x128, BK=64 halves. 128 threads, 4 warps 2x2, warp tile 64x64.
// smem rows: 64 halves + 8 pad = 72 halves (36 words) -> ldmatrix conflict-free.
// 2-stage cp.async pipeline, 2 CTAs/SM.
// MODE 0: QKV (fp16 head-layout out, z selects W/C, Q scaled)
// MODE 1: out-projection (f32 out)
// ---------------------------------------------------------------------------
#define GM 128
#define GN 128
#define GKH 64
#define GSTW 36
#define STAGE_W (GM * GSTW)                 // words per operand per stage
#define NKT (E_ / GKH)                      // 16
#define GEMM_SMEM (2 * 2 * STAGE_W * 4)     // 73728 B

template<int MODE>
__global__ __launch_bounds__(128)
void gemm_h_kernel(const __half* __restrict__ Ah,
                   const __half* __restrict__ Wq, const __half* __restrict__ Wk,
                   const __half* __restrict__ Wv,
                   __half* __restrict__ Cq, __half* __restrict__ Ck,
                   __half* __restrict__ Cv, float* __restrict__ Cf)
{
    extern __shared__ uint32_t dsm[];

    const __half* Wh = (MODE == 1) ? Wq
                     : (blockIdx.z == 0) ? Wq : (blockIdx.z == 1) ? Wk : Wv;
    __half* Ch = (blockIdx.z == 0) ? Cq : (blockIdx.z == 1) ? Ck : Cv;
    const float oscale = (MODE == 0 && blockIdx.z == 0) ? QSCALE_ : 1.0f;

    const int tid  = threadIdx.x;
    const int wid  = tid >> 5;
    const int lane = tid & 31;
    const int g    = lane >> 2;
    const int t    = lane & 3;
    const int wm   = (wid & 1) * 64;
    const int wn   = (wid >> 1) * 64;
    const int m0   = blockIdx.y * GM;
    const int n0   = blockIdx.x * GN;

    const uint32_t sbase = s2u(dsm);
    // stage s: A at s*2*STAGE_W, W at s*2*STAGE_W + STAGE_W (word offsets)
    const uint32_t aoff = (((lane & 15) * GSTW) + ((lane >> 4) * 4)) * 4u;
    const uint32_t boff = ((((lane >> 4) * 8 + (lane & 7)) * GSTW)
                          + (((lane >> 3) & 1) * 4)) * 4u;

    // cp.async role: 8 16B-chunks per operand per tile; 8 threads cover a row.
    const int crow = tid >> 3;      // base row 0..15
    const int cchk = tid & 7;       // chunk in row

    float acc[4][8][4];
    #pragma unroll
    for (int mi = 0; mi < 4; mi++)
        #pragma unroll
        for (int ni = 0; ni < 8; ni++)
            #pragma unroll
            for (int r = 0; r < 4; r++) acc[mi][ni][r] = 0.0f;

    // issue one stage of copies for k-tile kt into stage s
    auto issue = [&](int kt, int s) {
        const uint32_t sa = sbase + (uint32_t)(s * 2 * STAGE_W) * 4u;
        const uint32_t sw = sa + (uint32_t)STAGE_W * 4u;
        const __half* Agp = Ah + (size_t)(m0 + crow) * E_ + kt * GKH + cchk * 8;
        const __half* Wgp = Wh + (size_t)(n0 + crow) * E_ + kt * GKH + cchk * 8;
        #pragma unroll
        for (int i = 0; i < 8; i++) {
            const uint32_t so = (uint32_t)((crow + i * 16) * GSTW + cchk * 4) * 4u;
            cp16(sa + so, Agp + (size_t)(i * 16) * E_);
            cp16(sw + so, Wgp + (size_t)(i * 16) * E_);
        }
        CP_COMMIT();
    };

    issue(0, 0);
    issue(1, 1);

    for (int kt = 0; kt < NKT; kt++) {
        const int cur = kt & 1;
        if (kt + 2 < NKT) { CP_WAIT1(); } else { CP_WAIT0(); }
        __syncthreads();

        const uint32_t bufA = sbase + (uint32_t)(cur * 2 * STAGE_W) * 4u;
        const uint32_t bufW = bufA + (uint32_t)STAGE_W * 4u;
        #pragma unroll
        for (int ks = 0; ks < 4; ks++) {
            const uint32_t kb = ks * 32u;          // 8 words = 16 halves
            uint32_t a[4][4];
            #pragma unroll
            for (int mi = 0; mi < 4; mi++)
                ldsm_x4(a[mi][0], a[mi][1], a[mi][2], a[mi][3],
                        bufA + aoff + (uint32_t)((wm + mi * 16) * GSTW) * 4u + kb);
            uint32_t b[8][2];
            #pragma unroll
            for (int pr = 0; pr < 4; pr++)
                ldsm_x4(b[2*pr][0], b[2*pr][1], b[2*pr+1][0], b[2*pr+1][1],
                        bufW + boff + (uint32_t)((wn + pr * 16) * GSTW) * 4u + kb);
            #pragma unroll
            for (int mi = 0; mi < 4; mi++)
                #pragma unroll
                for (int ni = 0; ni < 8; ni++)
                    mma_f16(acc[mi][ni], a[mi], b[ni][0], b[ni][1]);
        }
        __syncthreads();
        if (kt + 2 < NKT) issue(kt + 2, cur);
    }

    #pragma unroll
    for (int mi = 0; mi < 4; mi++) {
        #pragma unroll
        for (int ni = 0; ni < 8; ni++) {
            const int col = n0 + wn + ni * 8 + 2 * t;
            #pragma unroll
            for (int half = 0; half < 2; half++) {
                const int row = m0 + wm + mi * 16 + g + half * 8;
                if (MODE == 0) {
                    const int b = row >> 11;
                    const int s = row & (S_ - 1);
                    const int h = col >> 6;
                    const int d = col & (D_ - 1);
                    uint32_t hv = packh2(acc[mi][ni][half*2+0] * oscale,
                                         acc[mi][ni][half*2+1] * oscale);
                    *(uint32_t*)(Ch + ((size_t)(b * H_ + h) * S_ + s) * D_ + d) = hv;
                } else {
                    float2 v;
                    v.x = acc[mi][ni][half * 2 + 0];
                    v.y = acc[mi][ni][half * 2 + 1];
                    *(float2*)(Cf + (size_t)row * E_ + col) = v;
                }
            }
        }
    }
}

// ---------------------------------------------------------------------------
// fp16 flash attention (unchanged from R9 passing version).
// ---------------------------------------------------------------------------
#define AQT 128
#define AKT 64
#define AST 36
#define SQ_WORDS (AQT * AST)
#define SK_WORDS (AKT * AST)
#define SV_WORDS (AKT * AST)
#define ATTN_SMEM ((SQ_WORDS + SK_WORDS + SV_WORDS) * 4)

__global__ __launch_bounds__(256, 2)
void attn_f16_kernel()
{
    extern __shared__ uint32_t dsm[];
    uint32_t* sQ  = dsm;
    uint32_t* sK  = dsm + SQ_WORDS;
    uint32_t* sVT = dsm + SQ_WORDS + SK_WORDS;

    const int tid  = threadIdx.x;
    const int w    = tid >> 5;
    const int lane = tid & 31;
    const int g    = lane >> 2;
    const int t    = lane & 3;
    const int bh   = blockIdx.y;
    const int q0   = blockIdx.x * AQT;
    const int qrow = q0 + w * 16;

    const uint32_t baseQ  = s2u(sQ);
    const uint32_t baseK  = s2u(sK);
    const uint32_t baseVT = s2u(sVT);
    const uint32_t aoffQ = (((w * 16 + (lane & 15)) * AST) + ((lane >> 4) * 4)) * 4u;
    const uint32_t boffB = ((((lane >> 4) * 8 + (lane & 7)) * AST)
                           + (((lane >> 3) & 1) * 4)) * 4u;

    {
        const uint4* Qg = (const uint4*)(g_q + ((size_t)bh * S_ + q0) * D_);
        #pragma unroll
        for (int i = 0; i < 4; i++) {
            const int idx = tid + i * 256;
            const int r = idx >> 3, c = idx & 7;
            *(uint4*)&sQ[r * AST + c * 4] = Qg[idx];
        }
    }

    float oacc[8][4];
    #pragma unroll
    for (int ni = 0; ni < 8; ni++)
        #pragma unroll
        for (int r = 0; r < 4; r++) oacc[ni][r] = 0.0f;

    float mA = -1e30f, mB = -1e30f, lA = 0.0f, lB = 0.0f;

    const __half* Kb = g_k + (size_t)bh * S_ * D_;
    const __half* Vb = g_v + (size_t)bh * S_ * D_;

    const int vp = tid & 31;
    const int vq = tid >> 5;

    for (int j0 = 0; j0 < S_; j0 += AKT) {
        __syncthreads();
        {
            const uint4* Kg = (const uint4*)(Kb + (size_t)j0 * D_);
            #pragma unroll
            for (int i = 0; i < 2; i++) {
                const int idx = tid + i * 256;
                const int r = idx >> 3, c = idx & 7;
                *(uint4*)&sK[r * AST + c * 4] = Kg[idx];
            }
        }
        {
            const uint4 va = *(const uint4*)(Vb + (size_t)(j0 + 2 * vp) * D_ + vq * 8);
            const uint4 vb = *(const uint4*)(Vb + (size_t)(j0 + 2 * vp + 1) * D_ + vq * 8);
            const int db = vq * 8;
            sVT[(db + 0) * AST + vp] = prmt(va.x, vb.x, 0x5410);
            sVT[(db + 1) * AST + vp] = prmt(va.x, vb.x, 0x7632);
            sVT[(db + 2) * AST + vp] = prmt(va.y, vb.y, 0x5410);
            sVT[(db + 3) * AST + vp] = prmt(va.y, vb.y, 0x7632);
            sVT[(db + 4) * AST + vp] = prmt(va.z, vb.z, 0x5410);
            sVT[(db + 5) * AST + vp] = prmt(va.z, vb.z, 0x7632);
            sVT[(db + 6) * AST + vp] = prmt(va.w, vb.w, 0x5410);
            sVT[(db + 7) * AST + vp] = prmt(va.w, vb.w, 0x7632);
        }
        __syncthreads();

        float sc[8][4];
        #pragma unroll
        for (int ni = 0; ni < 8; ni++)
            #pragma unroll
            for (int r = 0; r < 4; r++) sc[ni][r] = 0.0f;

        #pragma unroll
        for (int kc = 0; kc < 4; kc++) {
            const uint32_t kb = kc * 32u;
            uint32_t a[4];
            ldsm_x4(a[0], a[1], a[2], a[3], baseQ + aoffQ + kb);
            #pragma unroll
            for (int pr = 0; pr < 4; pr++) {
                uint32_t b0, b1, b2, b3;
                ldsm_x4(b0, b1, b2, b3,
                        baseK + boffB + (uint32_t)(pr * 16 * AST) * 4u + kb);
                mma_f16(sc[2*pr],     a, b0, b1);
                mma_f16(sc[2*pr + 1], a, b2, b3);
            }
        }

        float rmA = -1e30f, rmB = -1e30f;
        #pragma unroll
        for (int ni = 0; ni < 8; ni++) {
            rmA = fmaxf(rmA, fmaxf(sc[ni][0], sc[ni][1]));
            rmB = fmaxf(rmB, fmaxf(sc[ni][2], sc[ni][3]));
        }
        rmA = fmaxf(rmA, __shfl_xor_sync(0xffffffffu, rmA, 1));
        rmA = fmaxf(rmA, __shfl_xor_sync(0xffffffffu, rmA, 2));
        rmB = fmaxf(rmB, __shfl_xor_sync(0xffffffffu, rmB, 1));
        rmB = fmaxf(rmB, __shfl_xor_sync(0xffffffffu, rmB, 2));

        const float nmA = fmaxf(mA, rmA);
        const float nmB = fmaxf(mB, rmB);
        const float cfA = exp2f(mA - nmA);
        const float cfB = exp2f(mB - nmB);
        mA = nmA; mB = nmB;

        float rsA = 0.0f, rsB = 0.0f;
        #pragma unroll
        for (int ni = 0; ni < 8; ni++) {
            sc[ni][0] = exp2f(sc[ni][0] - mA); rsA += sc[ni][0];
            sc[ni][1] = exp2f(sc[ni][1] - mA); rsA += sc[ni][1];
            sc[ni][2] = exp2f(sc[ni][2] - mB); rsB += sc[ni][2];
            sc[ni][3] = exp2f(sc[ni][3] - mB); rsB += sc[ni][3];
        }
        rsA += __shfl_xor_sync(0xffffffffu, rsA, 1);
        rsA += __shfl_xor_sync(0xffffffffu, rsA, 2);
        rsB += __shfl_xor_sync(0xffffffffu, rsB, 1);
        rsB += __shfl_xor_sync(0xffffffffu, rsB, 2);
        lA = lA * cfA + rsA;
        lB = lB * cfB + rsB;

        #pragma unroll
        for (int ni = 0; ni < 8; ni++) {
            oacc[ni][0] *= cfA; oacc[ni][1] *= cfA;
            oacc[ni][2] *= cfB; oacc[ni][3] *= cfB;
        }

        #pragma unroll
        for (int kc = 0; kc < 4; kc++) {
            uint32_t ap[4];
            ap[0] = packh2(sc[2 * kc][0],     sc[2 * kc][1]);
            ap[1] = packh2(sc[2 * kc][2],     sc[2 * kc][3]);
            ap[2] = packh2(sc[2 * kc + 1][0], sc[2 * kc + 1][1]);
            ap[3] = packh2(sc[2 * kc + 1][2], sc[2 * kc + 1][3]);
            const uint32_t kb = kc * 32u;
            #pragma unroll
            for (int pr = 0; pr < 4; pr++) {
                uint32_t b0, b1, b2, b3;
                ldsm_x4(b0, b1, b2, b3,
                        baseVT + boffB + (uint32_t)(pr * 16 * AST) * 4u + kb);
                mma_f16(oacc[2*pr],     ap, b0, b1);
                mma_f16(oacc[2*pr + 1], ap, b2, b3);
            }
        }
    }

    const float ivA = 1.0f / lA;
    const float ivB = 1.0f / lB;
    const int b = bh / H_;
    const int h = bh % H_;
    __half* OA = g_att + ((size_t)(b * S_ + qrow + g    ) * E_) + h * D_;
    __half* OB = g_att + ((size_t)(b * S_ + qrow + g + 8) * E_) + h * D_;
    #pragma unroll
    for (int ni = 0; ni < 8; ni++) {
        *(uint32_t*)(OA + ni * 8 + 2 * t) = packh2(oacc[ni][0] * ivA, oacc[ni][1] * ivA);
        *(uint32_t*)(OB + ni * 8 + 2 * t) = packh2(oacc[ni][2] * ivB, oacc[ni][3] * ivB);
    }
}

// ---------------------------------------------------------------------------
// Launch
// ---------------------------------------------------------------------------
extern "C" void kernel_launch(void* const* d_in, const int* in_sizes, int n_in,
                              void* d_out, int out_size)
{
    (void)in_sizes; (void)n_in; (void)out_size;
    const float* x  = (const float*)d_in[0];
    const float* wq = (const float*)d_in[1];
    const float* wk = (const float*)d_in[2];
    const float* wv = (const float*)d_in[3];
    const float* wo = (const float*)d_in[4];
    float* out = (float*)d_out;

    __half *px, *pwq, *pwk, *pwv, *pwo, *pq, *pk, *pv, *pa;
    cudaGetSymbolAddress((void**)&px,  g_x);
    cudaGetSymbolAddress((void**)&pwq, g_wq);
    cudaGetSymbolAddress((void**)&pwk, g_wk);
    cudaGetSymbolAddress((void**)&pwv, g_wv);
    cudaGetSymbolAddress((void**)&pwo, g_wo);
    cudaGetSymbolAddress((void**)&pq,  g_q);
    cudaGetSymbolAddress((void**)&pk,  g_k);
    cudaGetSymbolAddress((void**)&pv,  g_v);
    cudaGetSymbolAddress((void**)&pa,  g_att);

    // f32 -> f16 conversions
    const int nx4 = M_ * E_ / 4, nw4 = E_ * E_ / 4;
    f2h_kernel<<<(nx4 + 255) / 256, 256>>>(x,  px,  nx4);
    f2h_kernel<<<(nw4 + 255) / 256, 256>>>(wq, pwq, nw4);
    f2h_kernel<<<(nw4 + 255) / 256, 256>>>(wk, pwk, nw4);
    f2h_kernel<<<(nw4 + 255) / 256, 256>>>(wv, pwv, nw4);
    f2h_kernel<<<(nw4 + 255) / 256, 256>>>(wo, pwo, nw4);

    cudaFuncSetAttribute(gemm_h_kernel<0>,
                         cudaFuncAttributeMaxDynamicSharedMemorySize, GEMM_SMEM);
    cudaFuncSetAttribute(gemm_h_kernel<1>,
                         cudaFuncAttributeMaxDynamicSharedMemorySize, GEMM_SMEM);

    gemm_h_kernel<0><<<dim3(E_ / GN, M_ / GM, 3), 128, GEMM_SMEM>>>(
        px, pwq, pwk, pwv, pq, pk, pv, nullptr);

    cudaFuncSetAttribute(attn_f16_kernel,
                         cudaFuncAttributeMaxDynamicSharedMemorySize, ATTN_SMEM);
    attn_f16_kernel<<<dim3(S_ / AQT, B_ * H_), 256, ATTN_SMEM>>>();

    gemm_h_kernel<1><<<dim3(E_ / GN, M_ / GM, 1), 128, GEMM_SMEM>>>(
        pa, pwo, nullptr, nullptr, nullptr, nullptr, nullptr, out);
}

// round 11
// speedup vs baseline: 10.1207x; 1.1044x over previous
#include <cuda_runtime.h>
#include <cuda_fp16.h>
#include <math.h>
#include <stdint.h>

#define B_ 2
#define S_ 2048
#define E_ 1024
#define H_ 16
#define D_ 64
#define M_ (B_*S_)
#define QSCALE_ 0.18033688011112042f   // 0.125 * log2(e)

__device__ __half g_x [M_*E_];
__device__ __half g_wq[E_*E_];
__device__ __half g_wk[E_*E_];
__device__ __half g_wv[E_*E_];
__device__ __half g_wo[E_*E_];
__device__ __half g_q[B_*H_*S_*D_];
__device__ __half g_k[B_*H_*S_*D_];
__device__ __half g_v[B_*H_*S_*D_];
__device__ __half g_att[B_*S_*E_];

// ---------------------------------------------------------------------------
// helpers
// ---------------------------------------------------------------------------
__device__ __forceinline__ uint32_t packh2(float lo, float hi) {
    uint32_t r;
    asm("cvt.rn.f16x2.f32 %0, %1, %2;" : "=r"(r) : "f"(hi), "f"(lo));
    return r;
}

__device__ __forceinline__ void mma_f16(float c[4], const uint32_t a[4],
                                        uint32_t b0, uint32_t b1) {
    asm volatile(
        "mma.sync.aligned.m16n8k16.row.col.f32.f16.f16.f32 "
        "{%0,%1,%2,%3}, {%4,%5,%6,%7}, {%8,%9}, {%0,%1,%2,%3};"
        : "+f"(c[0]), "+f"(c[1]), "+f"(c[2]), "+f"(c[3])
        : "r"(a[0]), "r"(a[1]), "r"(a[2]), "r"(a[3]), "r"(b0), "r"(b1));
}

__device__ __forceinline__ void ldsm_x4(uint32_t& r0, uint32_t& r1,
                                        uint32_t& r2, uint32_t& r3,
                                        uint32_t addr) {
    asm volatile("ldmatrix.sync.aligned.m8n8.x4.shared.b16 {%0,%1,%2,%3}, [%4];"
                 : "=r"(r0), "=r"(r1), "=r"(r2), "=r"(r3) : "r"(addr));
}

__device__ __forceinline__ void ldsm_x4_t(uint32_t& r0, uint32_t& r1,
                                          uint32_t& r2, uint32_t& r3,
                                          uint32_t addr) {
    asm volatile("ldmatrix.sync.aligned.m8n8.x4.trans.shared.b16 {%0,%1,%2,%3}, [%4];"
                 : "=r"(r0), "=r"(r1), "=r"(r2), "=r"(r3) : "r"(addr));
}

__device__ __forceinline__ uint32_t s2u(const void* p) {
    uint32_t a;
    asm("{ .reg .u64 t; cvta.to.shared.u64 t, %1; cvt.u32.u64 %0, t; }"
        : "=r"(a) : "l"(p));
    return a;
}

__device__ __forceinline__ void cp16(uint32_t smem, const void* g) {
    asm volatile("cp.async.ca.shared.global [%0], [%1], 16;"
                 :: "r"(smem), "l"(g) : "memory");
}
#define CP_COMMIT() asm volatile("cp.async.commit_group;" ::: "memory")
#define CP_WAIT1()  asm volatile("cp.async.wait_group 1;" ::: "memory")
#define CP_WAIT0()  asm volatile("cp.async.wait_group 0;" ::: "memory")

// ---------------------------------------------------------------------------
// f32 -> f16 conversion
// ---------------------------------------------------------------------------
__global__ void f2h_kernel(const float* __restrict__ src, __half* __restrict__ dst,
                           int n4)
{
    int i = blockIdx.x * blockDim.x + threadIdx.x;
    if (i < n4) {
        float4 v = ((const float4*)src)[i];
        uint2 o;
        o.x = packh2(v.x, v.y);
        o.y = packh2(v.z, v.w);
        ((uint2*)dst)[i] = o;
    }
}

// ---------------------------------------------------------------------------
// fp16 GEMM, 3-stage cp.async pipeline, ONE sync per k-tile.
// Block 128x128, BK=64 halves. 128 threads, 4 warps 2x2, warp tile 64x64.
// smem rows 72 halves (36 words) -> ldmatrix conflict-free.
// MODE 0: QKV (fp16 head layout out, z selects); MODE 1: out-proj (f32 out).
// ---------------------------------------------------------------------------
#define GM 128
#define GN 128
#define GKH 64
#define GSTW 36
#define STAGE_W (GM * GSTW)                 // 4608 words per operand
#define NKT (E_ / GKH)                      // 16
#define GEMM_SMEM (3 * 2 * STAGE_W * 4)     // 110592 B

template<int MODE>
__global__ __launch_bounds__(128)
void gemm_h_kernel(const __half* __restrict__ Ah,
                   const __half* __restrict__ Wq, const __half* __restrict__ Wk,
                   const __half* __restrict__ Wv,
                   __half* __restrict__ Cq, __half* __restrict__ Ck,
                   __half* __restrict__ Cv, float* __restrict__ Cf)
{
    extern __shared__ uint32_t dsm[];

    const __half* Wh = (MODE == 1) ? Wq
                     : (blockIdx.z == 0) ? Wq : (blockIdx.z == 1) ? Wk : Wv;
    __half* Ch = (blockIdx.z == 0) ? Cq : (blockIdx.z == 1) ? Ck : Cv;
    const float oscale = (MODE == 0 && blockIdx.z == 0) ? QSCALE_ : 1.0f;

    const int tid  = threadIdx.x;
    const int wid  = tid >> 5;
    const int lane = tid & 31;
    const int g    = lane >> 2;
    const int t    = lane & 3;
    const int wm   = (wid & 1) * 64;
    const int wn   = (wid >> 1) * 64;
    const int m0   = blockIdx.y * GM;
    const int n0   = blockIdx.x * GN;

    const uint32_t sbase = s2u(dsm);
    const uint32_t aoff = (((lane & 15) * GSTW) + ((lane >> 4) * 4)) * 4u;
    const uint32_t boff = ((((lane >> 4) * 8 + (lane & 7)) * GSTW)
                          + (((lane >> 3) & 1) * 4)) * 4u;

    const int crow = tid >> 3;
    const int cchk = tid & 7;

    float acc[4][8][4];
    #pragma unroll
    for (int mi = 0; mi < 4; mi++)
        #pragma unroll
        for (int ni = 0; ni < 8; ni++)
            #pragma unroll
            for (int r = 0; r < 4; r++) acc[mi][ni][r] = 0.0f;

    auto issue = [&](int kt, int s) {
        const uint32_t sa = sbase + (uint32_t)(s * 2 * STAGE_W) * 4u;
        const uint32_t sw = sa + (uint32_t)STAGE_W * 4u;
        const __half* Agp = Ah + (size_t)(m0 + crow) * E_ + kt * GKH + cchk * 8;
        const __half* Wgp = Wh + (size_t)(n0 + crow) * E_ + kt * GKH + cchk * 8;
        #pragma unroll
        for (int i = 0; i < 8; i++) {
            const uint32_t so = (uint32_t)((crow + i * 16) * GSTW + cchk * 4) * 4u;
            cp16(sa + so, Agp + (size_t)(i * 16) * E_);
            cp16(sw + so, Wgp + (size_t)(i * 16) * E_);
        }
        CP_COMMIT();
    };

    issue(0, 0);
    issue(1, 1);

    for (int kt = 0; kt < NKT; kt++) {
        if (kt + 1 < NKT) { CP_WAIT1(); } else { CP_WAIT0(); }
        __syncthreads();
        if (kt + 2 < NKT) {
            int s = kt + 2; s -= (s >= 3) ? 3 : 0; s -= (s >= 3) ? 3 : 0;
            issue(kt + 2, (kt + 2) % 3);
        }

        const int cs = kt % 3;
        const uint32_t bufA = sbase + (uint32_t)(cs * 2 * STAGE_W) * 4u;
        const uint32_t bufW = bufA + (uint32_t)STAGE_W * 4u;
        #pragma unroll
        for (int ks = 0; ks < 4; ks++) {
            const uint32_t kb = ks * 32u;
            uint32_t a[4][4];
            #pragma unroll
            for (int mi = 0; mi < 4; mi++)
                ldsm_x4(a[mi][0], a[mi][1], a[mi][2], a[mi][3],
                        bufA + aoff + (uint32_t)((wm + mi * 16) * GSTW) * 4u + kb);
            uint32_t b[8][2];
            #pragma unroll
            for (int pr = 0; pr < 4; pr++)
                ldsm_x4(b[2*pr][0], b[2*pr][1], b[2*pr+1][0], b[2*pr+1][1],
                        bufW + boff + (uint32_t)((wn + pr * 16) * GSTW) * 4u + kb);
            #pragma unroll
            for (int mi = 0; mi < 4; mi++)
                #pragma unroll
                for (int ni = 0; ni < 8; ni++)
                    mma_f16(acc[mi][ni], a[mi], b[ni][0], b[ni][1]);
        }
    }

    #pragma unroll
    for (int mi = 0; mi < 4; mi++) {
        #pragma unroll
        for (int ni = 0; ni < 8; ni++) {
            const int col = n0 + wn + ni * 8 + 2 * t;
            #pragma unroll
            for (int half = 0; half < 2; half++) {
                const int row = m0 + wm + mi * 16 + g + half * 8;
                if (MODE == 0) {
                    const int b = row >> 11;
                    const int s = row & (S_ - 1);
                    const int h = col >> 6;
                    const int d = col & (D_ - 1);
                    uint32_t hv = packh2(acc[mi][ni][half*2+0] * oscale,
                                         acc[mi][ni][half*2+1] * oscale);
                    *(uint32_t*)(Ch + ((size_t)(b * H_ + h) * S_ + s) * D_ + d) = hv;
                } else {
                    float2 v;
                    v.x = acc[mi][ni][half * 2 + 0];
                    v.y = acc[mi][ni][half * 2 + 1];
                    *(float2*)(Cf + (size_t)row * E_ + col) = v;
                }
            }
        }
    }
}

// ---------------------------------------------------------------------------
// fp16 flash attention, 3-stage cp.async K/V ring, one sync per tile.
// Block 128 q-rows, 256 threads. KV tile 64 keys. smem stride 36 words.
// Q fragments register-resident (loaded once). V via ldmatrix.x4.trans
// from row-major smem (no transpose staging).
// ---------------------------------------------------------------------------
#define AQT 128
#define AKT 64
#define AST 36
#define QW (AQT * AST)                       // 4608 words
#define KVW (AKT * AST)                      // 2304 words per operand
#define STG_W (2 * KVW)                      // K+V per stage
#define NT (S_ / AKT)                        // 32
#define ATTN_SMEM ((QW + 3 * STG_W) * 4)     // 73728 B

__global__ __launch_bounds__(256, 2)
void attn_f16_kernel()
{
    extern __shared__ uint32_t dsm[];

    const int tid  = threadIdx.x;
    const int w    = tid >> 5;
    const int lane = tid & 31;
    const int g    = lane >> 2;
    const int t    = lane & 3;
    const int bh   = blockIdx.y;
    const int q0   = blockIdx.x * AQT;
    const int qrow = q0 + w * 16;

    const uint32_t sbase = s2u(dsm);
    const uint32_t kvbase = sbase + (uint32_t)QW * 4u;
    // fragment lane offsets
    const uint32_t aoffQ = (((w * 16 + (lane & 15)) * AST) + ((lane >> 4) * 4)) * 4u;
    const uint32_t boffK = ((((lane >> 4) * 8 + (lane & 7)) * AST)
                           + (((lane >> 3) & 1) * 4)) * 4u;
    const uint32_t voffV = (((lane & 15) * AST) + ((lane >> 4) * 4)) * 4u;

    const __half* Kb = g_k + (size_t)bh * S_ * D_;
    const __half* Vb = g_v + (size_t)bh * S_ * D_;
    const int crow = tid >> 3;      // 0..31
    const int cchk = tid & 7;

    auto issue = [&](int jt, int s) {
        const uint32_t sk = kvbase + (uint32_t)(s * STG_W) * 4u;
        const uint32_t sv = sk + (uint32_t)KVW * 4u;
        const __half* Kg = Kb + (size_t)(jt * AKT + crow) * D_ + cchk * 8;
        const __half* Vg = Vb + (size_t)(jt * AKT + crow) * D_ + cchk * 8;
        #pragma unroll
        for (int i = 0; i < 2; i++) {
            const uint32_t so = (uint32_t)((crow + i * 32) * AST + cchk * 4) * 4u;
            cp16(sk + so, Kg + (size_t)(i * 32) * D_);
            cp16(sv + so, Vg + (size_t)(i * 32) * D_);
        }
        CP_COMMIT();
    };

    // ---- stage Q (direct stores) + start KV pipeline ----
    {
        const uint4* Qg = (const uint4*)(g_q + ((size_t)bh * S_ + q0) * D_);
        #pragma unroll
        for (int i = 0; i < 4; i++) {
            const int idx = tid + i * 256;
            const int r = idx >> 3, c = idx & 7;
            *(uint4*)&dsm[r * AST + c * 4] = Qg[idx];
        }
    }
    issue(0, 0);
    issue(1, 1);
    __syncthreads();

    // Q fragments -> registers (once)
    uint32_t aq[4][4];
    #pragma unroll
    for (int kc = 0; kc < 4; kc++)
        ldsm_x4(aq[kc][0], aq[kc][1], aq[kc][2], aq[kc][3],
                sbase + aoffQ + kc * 32u);

    float oacc[8][4];
    #pragma unroll
    for (int ni = 0; ni < 8; ni++)
        #pragma unroll
        for (int r = 0; r < 4; r++) oacc[ni][r] = 0.0f;

    float mA = -1e30f, mB = -1e30f, lA = 0.0f, lB = 0.0f;

    for (int jt = 0; jt < NT; jt++) {
        if (jt + 1 < NT) { CP_WAIT1(); } else { CP_WAIT0(); }
        __syncthreads();
        if (jt + 2 < NT) issue(jt + 2, (jt + 2) % 3);

        const int cs = jt % 3;
        const uint32_t baseK = kvbase + (uint32_t)(cs * STG_W) * 4u;
        const uint32_t baseV = baseK + (uint32_t)KVW * 4u;

        // ---- scores ----
        float sc[8][4];
        #pragma unroll
        for (int ni = 0; ni < 8; ni++)
            #pragma unroll
            for (int r = 0; r < 4; r++) sc[ni][r] = 0.0f;

        #pragma unroll
        for (int kc = 0; kc < 4; kc++) {
            const uint32_t kb = kc * 32u;
            #pragma unroll
            for (int pr = 0; pr < 4; pr++) {
                uint32_t b0, b1, b2, b3;
                ldsm_x4(b0, b1, b2, b3,
                        baseK + boffK + (uint32_t)(pr * 16 * AST) * 4u + kb);
                mma_f16(sc[2*pr],     aq[kc], b0, b1);
                mma_f16(sc[2*pr + 1], aq[kc], b2, b3);
            }
        }

        // ---- online softmax (base-2) ----
        float rmA = -1e30f, rmB = -1e30f;
        #pragma unroll
        for (int ni = 0; ni < 8; ni++) {
            rmA = fmaxf(rmA, fmaxf(sc[ni][0], sc[ni][1]));
            rmB = fmaxf(rmB, fmaxf(sc[ni][2], sc[ni][3]));
        }
        rmA = fmaxf(rmA, __shfl_xor_sync(0xffffffffu, rmA, 1));
        rmA = fmaxf(rmA, __shfl_xor_sync(0xffffffffu, rmA, 2));
        rmB = fmaxf(rmB, __shfl_xor_sync(0xffffffffu, rmB, 1));
        rmB = fmaxf(rmB, __shfl_xor_sync(0xffffffffu, rmB, 2));

        const float nmA = fmaxf(mA, rmA);
        const float nmB = fmaxf(mB, rmB);
        const float cfA = exp2f(mA - nmA);
        const float cfB = exp2f(mB - nmB);
        mA = nmA; mB = nmB;

        float rsA = 0.0f, rsB = 0.0f;
        #pragma unroll
        for (int ni = 0; ni < 8; ni++) {
            sc[ni][0] = exp2f(sc[ni][0] - mA); rsA += sc[ni][0];
            sc[ni][1] = exp2f(sc[ni][1] - mA); rsA += sc[ni][1];
            sc[ni][2] = exp2f(sc[ni][2] - mB); rsB += sc[ni][2];
            sc[ni][3] = exp2f(sc[ni][3] - mB); rsB += sc[ni][3];
        }
        rsA += __shfl_xor_sync(0xffffffffu, rsA, 1);
        rsA += __shfl_xor_sync(0xffffffffu, rsA, 2);
        rsB += __shfl_xor_sync(0xffffffffu, rsB, 1);
        rsB += __shfl_xor_sync(0xffffffffu, rsB, 2);
        lA = lA * cfA + rsA;
        lB = lB * cfB + rsB;

        #pragma unroll
        for (int ni = 0; ni < 8; ni++) {
            oacc[ni][0] *= cfA; oacc[ni][1] *= cfA;
            oacc[ni][2] *= cfB; oacc[ni][3] *= cfB;
        }

        // ---- O += P V (V via ldmatrix.trans from row-major smem) ----
        #pragma unroll
        for (int kc = 0; kc < 4; kc++) {
            uint32_t ap[4];
            ap[0] = packh2(sc[2 * kc][0],     sc[2 * kc][1]);
            ap[1] = packh2(sc[2 * kc][2],     sc[2 * kc][3]);
            ap[2] = packh2(sc[2 * kc + 1][0], sc[2 * kc + 1][1]);
            ap[3] = packh2(sc[2 * kc + 1][2], sc[2 * kc + 1][3]);
            const uint32_t krows = (uint32_t)(kc * 16 * AST) * 4u;
            #pragma unroll
            for (int npr = 0; npr < 4; npr++) {
                uint32_t b0, b1, b2, b3;
                ldsm_x4_t(b0, b1, b2, b3,
                          baseV + voffV + krows + npr * 32u);
                mma_f16(oacc[2*npr],     ap, b0, b1);
                mma_f16(oacc[2*npr + 1], ap, b2, b3);
            }
        }
    }

    // ---- epilogue ----
    const float ivA = 1.0f / lA;
    const float ivB = 1.0f / lB;
    const int b = bh / H_;
    const int h = bh % H_;
    __half* OA = g_att + ((size_t)(b * S_ + qrow + g    ) * E_) + h * D_;
    __half* OB = g_att + ((size_t)(b * S_ + qrow + g + 8) * E_) + h * D_;
    #pragma unroll
    for (int ni = 0; ni < 8; ni++) {
        *(uint32_t*)(OA + ni * 8 + 2 * t) = packh2(oacc[ni][0] * ivA, oacc[ni][1] * ivA);
        *(uint32_t*)(OB + ni * 8 + 2 * t) = packh2(oacc[ni][2] * ivB, oacc[ni][3] * ivB);
    }
}

// ---------------------------------------------------------------------------
// Launch
// ---------------------------------------------------------------------------
extern "C" void kernel_launch(void* const* d_in, const int* in_sizes, int n_in,
                              void* d_out, int out_size)
{
    (void)in_sizes; (void)n_in; (void)out_size;
    const float* x  = (const float*)d_in[0];
    const float* wq = (const float*)d_in[1];
    const float* wk = (const float*)d_in[2];
    const float* wv = (const float*)d_in[3];
    const float* wo = (const float*)d_in[4];
    float* out = (float*)d_out;

    __half *px, *pwq, *pwk, *pwv, *pwo, *pq, *pk, *pv, *pa;
    cudaGetSymbolAddress((void**)&px,  g_x);
    cudaGetSymbolAddress((void**)&pwq, g_wq);
    cudaGetSymbolAddress((void**)&pwk, g_wk);
    cudaGetSymbolAddress((void**)&pwv, g_wv);
    cudaGetSymbolAddress((void**)&pwo, g_wo);
    cudaGetSymbolAddress((void**)&pq,  g_q);
    cudaGetSymbolAddress((void**)&pk,  g_k);
    cudaGetSymbolAddress((void**)&pv,  g_v);
    cudaGetSymbolAddress((void**)&pa,  g_att);

    const int nx4 = M_ * E_ / 4, nw4 = E_ * E_ / 4;
    f2h_kernel<<<(nx4 + 255) / 256, 256>>>(x,  px,  nx4);
    f2h_kernel<<<(nw4 + 255) / 256, 256>>>(wq, pwq, nw4);
    f2h_kernel<<<(nw4 + 255) / 256, 256>>>(wk, pwk, nw4);
    f2h_kernel<<<(nw4 + 255) / 256, 256>>>(wv, pwv, nw4);
    f2h_kernel<<<(nw4 + 255) / 256, 256>>>(wo, pwo, nw4);

    cudaFuncSetAttribute(gemm_h_kernel<0>,
                         cudaFuncAttributeMaxDynamicSharedMemorySize, GEMM_SMEM);
    cudaFuncSetAttribute(gemm_h_kernel<1>,
                         cudaFuncAttributeMaxDynamicSharedMemorySize, GEMM_SMEM);

    gemm_h_kernel<0><<<dim3(E_ / GN, M_ / GM, 3), 128, GEMM_SMEM>>>(
        px, pwq, pwk, pwv, pq, pk, pv, nullptr);

    cudaFuncSetAttribute(attn_f16_kernel,
                         cudaFuncAttributeMaxDynamicSharedMemorySize, ATTN_SMEM);
    attn_f16_kernel<<<dim3(S_ / AQT, B_ * H_), 256, ATTN_SMEM>>>();

    gemm_h_kernel<1><<<dim3(E_ / GN, M_ / GM, 1), 128, GEMM_SMEM>>>(
        pa, pwo, nullptr, nullptr, nullptr, nullptr, nullptr, out);
}

// round 12
// speedup vs baseline: 10.8423x; 1.0713x over previous
#include <cuda_runtime.h>
#include <cuda_fp16.h>
#include <math.h>
#include <stdint.h>

#define B_ 2
#define S_ 2048
#define E_ 1024
#define H_ 16
#define D_ 64
#define M_ (B_*S_)
#define QSCALE_ 0.18033688011112042f   // 0.125 * log2(e)

__device__ __half g_x [M_*E_];
__device__ __half g_wq[E_*E_];
__device__ __half g_wk[E_*E_];
__device__ __half g_wv[E_*E_];
__device__ __half g_wo[E_*E_];
__device__ __half g_q[B_*H_*S_*D_];
__device__ __half g_k[B_*H_*S_*D_];
__device__ __half g_v[B_*H_*S_*D_];
__device__ __half g_att[B_*S_*E_];

// ---------------------------------------------------------------------------
// helpers
// ---------------------------------------------------------------------------
__device__ __forceinline__ uint32_t packh2(float lo, float hi) {
    uint32_t r;
    asm("cvt.rn.f16x2.f32 %0, %1, %2;" : "=r"(r) : "f"(hi), "f"(lo));
    return r;
}

__device__ __forceinline__ uint32_t h2exp2(uint32_t x) {
    uint32_t r;
    asm("ex2.approx.f16x2 %0, %1;" : "=r"(r) : "r"(x));
    return r;
}

__device__ __forceinline__ void mma_f16(float c[4], const uint32_t a[4],
                                        uint32_t b0, uint32_t b1) {
    asm volatile(
        "mma.sync.aligned.m16n8k16.row.col.f32.f16.f16.f32 "
        "{%0,%1,%2,%3}, {%4,%5,%6,%7}, {%8,%9}, {%0,%1,%2,%3};"
        : "+f"(c[0]), "+f"(c[1]), "+f"(c[2]), "+f"(c[3])
        : "r"(a[0]), "r"(a[1]), "r"(a[2]), "r"(a[3]), "r"(b0), "r"(b1));
}

__device__ __forceinline__ void ldsm_x4(uint32_t& r0, uint32_t& r1,
                                        uint32_t& r2, uint32_t& r3,
                                        uint32_t addr) {
    asm volatile("ldmatrix.sync.aligned.m8n8.x4.shared.b16 {%0,%1,%2,%3}, [%4];"
                 : "=r"(r0), "=r"(r1), "=r"(r2), "=r"(r3) : "r"(addr));
}

__device__ __forceinline__ void ldsm_x4_t(uint32_t& r0, uint32_t& r1,
                                          uint32_t& r2, uint32_t& r3,
                                          uint32_t addr) {
    asm volatile("ldmatrix.sync.aligned.m8n8.x4.trans.shared.b16 {%0,%1,%2,%3}, [%4];"
                 : "=r"(r0), "=r"(r1), "=r"(r2), "=r"(r3) : "r"(addr));
}

__device__ __forceinline__ uint32_t s2u(const void* p) {
    uint32_t a;
    asm("{ .reg .u64 t; cvta.to.shared.u64 t, %1; cvt.u32.u64 %0, t; }"
        : "=r"(a) : "l"(p));
    return a;
}

__device__ __forceinline__ void cp16(uint32_t smem, const void* g) {
    asm volatile("cp.async.ca.shared.global [%0], [%1], 16;"
                 :: "r"(smem), "l"(g) : "memory");
}
#define CP_COMMIT() asm volatile("cp.async.commit_group;" ::: "memory")
#define CP_WAIT1()  asm volatile("cp.async.wait_group 1;" ::: "memory")
#define CP_WAIT0()  asm volatile("cp.async.wait_group 0;" ::: "memory")

// ---------------------------------------------------------------------------
// merged f32 -> f16 conversion for x + 4 weights (one launch)
// ---------------------------------------------------------------------------
#define NX4 (M_ * E_ / 4)
#define NW4 (E_ * E_ / 4)
#define NTOT4 (NX4 + 4 * NW4)

__global__ void f2h_all_kernel(const float* __restrict__ x,
                               const float* __restrict__ wq,
                               const float* __restrict__ wk,
                               const float* __restrict__ wv,
                               const float* __restrict__ wo)
{
    int i = blockIdx.x * blockDim.x + threadIdx.x;
    if (i >= NTOT4) return;
    const float* src;
    __half* dst;
    int off;
    if (i < NX4) { src = x; dst = g_x; off = i; }
    else {
        int j = i - NX4;
        int sel = j / NW4;
        off = j - sel * NW4;
        src = (sel == 0) ? wq : (sel == 1) ? wk : (sel == 2) ? wv : wo;
        dst = (sel == 0) ? g_wq : (sel == 1) ? g_wk : (sel == 2) ? g_wv : g_wo;
    }
    float4 v = ((const float4*)src)[off];
    uint2 o;
    o.x = packh2(v.x, v.y);
    o.y = packh2(v.z, v.w);
    ((uint2*)dst)[off] = o;
}

// ---------------------------------------------------------------------------
// fp16 GEMM, 3-stage cp.async pipeline, ONE sync per k-tile (unchanged R11).
// ---------------------------------------------------------------------------
#define GM 128
#define GN 128
#define GKH 64
#define GSTW 36
#define STAGE_W (GM * GSTW)
#define NKT (E_ / GKH)
#define GEMM_SMEM (3 * 2 * STAGE_W * 4)

template<int MODE>
__global__ __launch_bounds__(128)
void gemm_h_kernel(const __half* __restrict__ Ah,
                   const __half* __restrict__ Wq, const __half* __restrict__ Wk,
                   const __half* __restrict__ Wv,
                   __half* __restrict__ Cq, __half* __restrict__ Ck,
                   __half* __restrict__ Cv, float* __restrict__ Cf)
{
    extern __shared__ uint32_t dsm[];

    const __half* Wh = (MODE == 1) ? Wq
                     : (blockIdx.z == 0) ? Wq : (blockIdx.z == 1) ? Wk : Wv;
    __half* Ch = (blockIdx.z == 0) ? Cq : (blockIdx.z == 1) ? Ck : Cv;
    const float oscale = (MODE == 0 && blockIdx.z == 0) ? QSCALE_ : 1.0f;

    const int tid  = threadIdx.x;
    const int wid  = tid >> 5;
    const int lane = tid & 31;
    const int g    = lane >> 2;
    const int t    = lane & 3;
    const int wm   = (wid & 1) * 64;
    const int wn   = (wid >> 1) * 64;
    const int m0   = blockIdx.y * GM;
    const int n0   = blockIdx.x * GN;

    const uint32_t sbase = s2u(dsm);
    const uint32_t aoff = (((lane & 15) * GSTW) + ((lane >> 4) * 4)) * 4u;
    const uint32_t boff = ((((lane >> 4) * 8 + (lane & 7)) * GSTW)
                          + (((lane >> 3) & 1) * 4)) * 4u;

    const int crow = tid >> 3;
    const int cchk = tid & 7;

    float acc[4][8][4];
    #pragma unroll
    for (int mi = 0; mi < 4; mi++)
        #pragma unroll
        for (int ni = 0; ni < 8; ni++)
            #pragma unroll
            for (int r = 0; r < 4; r++) acc[mi][ni][r] = 0.0f;

    auto issue = [&](int kt, int s) {
        const uint32_t sa = sbase + (uint32_t)(s * 2 * STAGE_W) * 4u;
        const uint32_t sw = sa + (uint32_t)STAGE_W * 4u;
        const __half* Agp = Ah + (size_t)(m0 + crow) * E_ + kt * GKH + cchk * 8;
        const __half* Wgp = Wh + (size_t)(n0 + crow) * E_ + kt * GKH + cchk * 8;
        #pragma unroll
        for (int i = 0; i < 8; i++) {
            const uint32_t so = (uint32_t)((crow + i * 16) * GSTW + cchk * 4) * 4u;
            cp16(sa + so, Agp + (size_t)(i * 16) * E_);
            cp16(sw + so, Wgp + (size_t)(i * 16) * E_);
        }
        CP_COMMIT();
    };

    issue(0, 0);
    issue(1, 1);

    for (int kt = 0; kt < NKT; kt++) {
        if (kt + 1 < NKT) { CP_WAIT1(); } else { CP_WAIT0(); }
        __syncthreads();
        if (kt + 2 < NKT) issue(kt + 2, (kt + 2) % 3);

        const int cs = kt % 3;
        const uint32_t bufA = sbase + (uint32_t)(cs * 2 * STAGE_W) * 4u;
        const uint32_t bufW = bufA + (uint32_t)STAGE_W * 4u;
        #pragma unroll
        for (int ks = 0; ks < 4; ks++) {
            const uint32_t kb = ks * 32u;
            uint32_t a[4][4];
            #pragma unroll
            for (int mi = 0; mi < 4; mi++)
                ldsm_x4(a[mi][0], a[mi][1], a[mi][2], a[mi][3],
                        bufA + aoff + (uint32_t)((wm + mi * 16) * GSTW) * 4u + kb);
            uint32_t b[8][2];
            #pragma unroll
            for (int pr = 0; pr < 4; pr++)
                ldsm_x4(b[2*pr][0], b[2*pr][1], b[2*pr+1][0], b[2*pr+1][1],
                        bufW + boff + (uint32_t)((wn + pr * 16) * GSTW) * 4u + kb);
            #pragma unroll
            for (int mi = 0; mi < 4; mi++)
                #pragma unroll
                for (int ni = 0; ni < 8; ni++)
                    mma_f16(acc[mi][ni], a[mi], b[ni][0], b[ni][1]);
        }
    }

    #pragma unroll
    for (int mi = 0; mi < 4; mi++) {
        #pragma unroll
        for (int ni = 0; ni < 8; ni++) {
            const int col = n0 + wn + ni * 8 + 2 * t;
            #pragma unroll
            for (int half = 0; half < 2; half++) {
                const int row = m0 + wm + mi * 16 + g + half * 8;
                if (MODE == 0) {
                    const int b = row >> 11;
                    const int s = row & (S_ - 1);
                    const int h = col >> 6;
                    const int d = col & (D_ - 1);
                    uint32_t hv = packh2(acc[mi][ni][half*2+0] * oscale,
                                         acc[mi][ni][half*2+1] * oscale);
                    *(uint32_t*)(Ch + ((size_t)(b * H_ + h) * S_ + s) * D_ + d) = hv;
                } else {
                    float2 v;
                    v.x = acc[mi][ni][half * 2 + 0];
                    v.y = acc[mi][ni][half * 2 + 1];
                    *(float2*)(Cf + (size_t)row * E_ + col) = v;
                }
            }
        }
    }
}

// ---------------------------------------------------------------------------
// fp16 flash attention: 3-stage cp.async KV ring, one sync/tile, register Q,
// ldmatrix.trans V, ex2.approx.f16x2 softmax, ones-MMA row sums.
// ---------------------------------------------------------------------------
#define AQT 128
#define AKT 64
#define AST 36
#define QW (AQT * AST)
#define KVW (AKT * AST)
#define STG_W (2 * KVW)
#define NT (S_ / AKT)
#define ATTN_SMEM ((QW + 3 * STG_W) * 4)
#define ONES2 0x3C003C00u

__global__ __launch_bounds__(256, 2)
void attn_f16_kernel()
{
    extern __shared__ uint32_t dsm[];

    const int tid  = threadIdx.x;
    const int w    = tid >> 5;
    const int lane = tid & 31;
    const int g    = lane >> 2;
    const int t    = lane & 3;
    const int bh   = blockIdx.y;
    const int q0   = blockIdx.x * AQT;
    const int qrow = q0 + w * 16;

    const uint32_t sbase = s2u(dsm);
    const uint32_t kvbase = sbase + (uint32_t)QW * 4u;
    const uint32_t aoffQ = (((w * 16 + (lane & 15)) * AST) + ((lane >> 4) * 4)) * 4u;
    const uint32_t boffK = ((((lane >> 4) * 8 + (lane & 7)) * AST)
                           + (((lane >> 3) & 1) * 4)) * 4u;
    const uint32_t voffV = (((lane & 15) * AST) + ((lane >> 4) * 4)) * 4u;

    const __half* Kb = g_k + (size_t)bh * S_ * D_;
    const __half* Vb = g_v + (size_t)bh * S_ * D_;
    const int crow = tid >> 3;
    const int cchk = tid & 7;

    auto issue = [&](int jt, int s) {
        const uint32_t sk = kvbase + (uint32_t)(s * STG_W) * 4u;
        const uint32_t sv = sk + (uint32_t)KVW * 4u;
        const __half* Kg = Kb + (size_t)(jt * AKT + crow) * D_ + cchk * 8;
        const __half* Vg = Vb + (size_t)(jt * AKT + crow) * D_ + cchk * 8;
        #pragma unroll
        for (int i = 0; i < 2; i++) {
            const uint32_t so = (uint32_t)((crow + i * 32) * AST + cchk * 4) * 4u;
            cp16(sk + so, Kg + (size_t)(i * 32) * D_);
            cp16(sv + so, Vg + (size_t)(i * 32) * D_);
        }
        CP_COMMIT();
    };

    {
        const uint4* Qg = (const uint4*)(g_q + ((size_t)bh * S_ + q0) * D_);
        #pragma unroll
        for (int i = 0; i < 4; i++) {
            const int idx = tid + i * 256;
            const int r = idx >> 3, c = idx & 7;
            *(uint4*)&dsm[r * AST + c * 4] = Qg[idx];
        }
    }
    issue(0, 0);
    issue(1, 1);
    __syncthreads();

    uint32_t aq[4][4];
    #pragma unroll
    for (int kc = 0; kc < 4; kc++)
        ldsm_x4(aq[kc][0], aq[kc][1], aq[kc][2], aq[kc][3],
                sbase + aoffQ + kc * 32u);

    float oacc[8][4];
    #pragma unroll
    for (int ni = 0; ni < 8; ni++)
        #pragma unroll
        for (int r = 0; r < 4; r++) oacc[ni][r] = 0.0f;
    float lacc[4] = {0.0f, 0.0f, 0.0f, 0.0f};

    float mA = -1e30f, mB = -1e30f;

    for (int jt = 0; jt < NT; jt++) {
        if (jt + 1 < NT) { CP_WAIT1(); } else { CP_WAIT0(); }
        __syncthreads();
        if (jt + 2 < NT) issue(jt + 2, (jt + 2) % 3);

        const int cs = jt % 3;
        const uint32_t baseK = kvbase + (uint32_t)(cs * STG_W) * 4u;
        const uint32_t baseV = baseK + (uint32_t)KVW * 4u;

        // ---- scores ----
        float sc[8][4];
        #pragma unroll
        for (int ni = 0; ni < 8; ni++)
            #pragma unroll
            for (int r = 0; r < 4; r++) sc[ni][r] = 0.0f;

        #pragma unroll
        for (int kc = 0; kc < 4; kc++) {
            const uint32_t kb = kc * 32u;
            #pragma unroll
            for (int pr = 0; pr < 4; pr++) {
                uint32_t b0, b1, b2, b3;
                ldsm_x4(b0, b1, b2, b3,
                        baseK + boffK + (uint32_t)(pr * 16 * AST) * 4u + kb);
                mma_f16(sc[2*pr],     aq[kc], b0, b1);
                mma_f16(sc[2*pr + 1], aq[kc], b2, b3);
            }
        }

        // ---- online softmax (base-2, fp16 exp) ----
        float rmA = -1e30f, rmB = -1e30f;
        #pragma unroll
        for (int ni = 0; ni < 8; ni++) {
            rmA = fmaxf(rmA, fmaxf(sc[ni][0], sc[ni][1]));
            rmB = fmaxf(rmB, fmaxf(sc[ni][2], sc[ni][3]));
        }
        rmA = fmaxf(rmA, __shfl_xor_sync(0xffffffffu, rmA, 1));
        rmA = fmaxf(rmA, __shfl_xor_sync(0xffffffffu, rmA, 2));
        rmB = fmaxf(rmB, __shfl_xor_sync(0xffffffffu, rmB, 1));
        rmB = fmaxf(rmB, __shfl_xor_sync(0xffffffffu, rmB, 2));

        const float nmA = fmaxf(mA, rmA);
        const float nmB = fmaxf(mB, rmB);
        const float cfA = exp2f(mA - nmA);
        const float cfB = exp2f(mB - nmB);
        mA = nmA; mB = nmB;

        lacc[0] *= cfA; lacc[1] *= cfA;
        lacc[2] *= cfB; lacc[3] *= cfB;
        #pragma unroll
        for (int ni = 0; ni < 8; ni++) {
            oacc[ni][0] *= cfA; oacc[ni][1] *= cfA;
            oacc[ni][2] *= cfB; oacc[ni][3] *= cfB;
        }

        // ---- P (fp16) + O += P V + l += P 1 ----
        #pragma unroll
        for (int kc = 0; kc < 4; kc++) {
            uint32_t ap[4];
            ap[0] = h2exp2(packh2(sc[2*kc][0]   - mA, sc[2*kc][1]   - mA));
            ap[1] = h2exp2(packh2(sc[2*kc][2]   - mB, sc[2*kc][3]   - mB));
            ap[2] = h2exp2(packh2(sc[2*kc+1][0] - mA, sc[2*kc+1][1] - mA));
            ap[3] = h2exp2(packh2(sc[2*kc+1][2] - mB, sc[2*kc+1][3] - mB));
            mma_f16(lacc, ap, ONES2, ONES2);
            const uint32_t krows = (uint32_t)(kc * 16 * AST) * 4u;
            #pragma unroll
            for (int npr = 0; npr < 4; npr++) {
                uint32_t b0, b1, b2, b3;
                ldsm_x4_t(b0, b1, b2, b3, baseV + voffV + krows + npr * 32u);
                mma_f16(oacc[2*npr],     ap, b0, b1);
                mma_f16(oacc[2*npr + 1], ap, b2, b3);
            }
        }
    }

    // ---- epilogue ----
    const float ivA = 1.0f / lacc[0];
    const float ivB = 1.0f / lacc[2];
    const int b = bh / H_;
    const int h = bh % H_;
    __half* OA = g_att + ((size_t)(b * S_ + qrow + g    ) * E_) + h * D_;
    __half* OB = g_att + ((size_t)(b * S_ + qrow + g + 8) * E_) + h * D_;
    #pragma unroll
    for (int ni = 0; ni < 8; ni++) {
        *(uint32_t*)(OA + ni * 8 + 2 * t) = packh2(oacc[ni][0] * ivA, oacc[ni][1] * ivA);
        *(uint32_t*)(OB + ni * 8 + 2 * t) = packh2(oacc[ni][2] * ivB, oacc[ni][3] * ivB);
    }
}

// ---------------------------------------------------------------------------
// Launch
// ---------------------------------------------------------------------------
extern "C" void kernel_launch(void* const* d_in, const int* in_sizes, int n_in,
                              void* d_out, int out_size)
{
    (void)in_sizes; (void)n_in; (void)out_size;
    const float* x  = (const float*)d_in[0];
    const float* wq = (const float*)d_in[1];
    const float* wk = (const float*)d_in[2];
    const float* wv = (const float*)d_in[3];
    const float* wo = (const float*)d_in[4];
    float* out = (float*)d_out;

    __half *px, *pwq, *pwk, *pwv, *pwo, *pq, *pk, *pv, *pa;
    cudaGetSymbolAddress((void**)&px,  g_x);
    cudaGetSymbolAddress((void**)&pwq, g_wq);
    cudaGetSymbolAddress((void**)&pwk, g_wk);
    cudaGetSymbolAddress((void**)&pwv, g_wv);
    cudaGetSymbolAddress((void**)&pwo, g_wo);
    cudaGetSymbolAddress((void**)&pq,  g_q);
    cudaGetSymbolAddress((void**)&pk,  g_k);
    cudaGetSymbolAddress((void**)&pv,  g_v);
    cudaGetSymbolAddress((void**)&pa,  g_att);

    f2h_all_kernel<<<(NTOT4 + 255) / 256, 256>>>(x, wq, wk, wv, wo);

    cudaFuncSetAttribute(gemm_h_kernel<0>,
                         cudaFuncAttributeMaxDynamicSharedMemorySize, GEMM_SMEM);
    cudaFuncSetAttribute(gemm_h_kernel<1>,
                         cudaFuncAttributeMaxDynamicSharedMemorySize, GEMM_SMEM);

    gemm_h_kernel<0><<<dim3(E_ / GN, M_ / GM, 3), 128, GEMM_SMEM>>>(
        px, pwq, pwk, pwv, pq, pk, pv, nullptr);

    cudaFuncSetAttribute(attn_f16_kernel,
                         cudaFuncAttributeMaxDynamicSharedMemorySize, ATTN_SMEM);
    attn_f16_kernel<<<dim3(S_ / AQT, B_ * H_), 256, ATTN_SMEM>>>();

    gemm_h_kernel<1><<<dim3(E_ / GN, M_ / GM, 1), 128, GEMM_SMEM>>>(
        pa, pwo, nullptr, nullptr, nullptr, nullptr, nullptr, out);
}

// round 14
// speedup vs baseline: 10.9861x; 1.0133x over previous
#include <cuda_runtime.h>
#include <cuda_fp16.h>
#include <math.h>
#include <stdint.h>

#define B_ 2
#define S_ 2048
#define E_ 1024
#define H_ 16
#define D_ 64
#define M_ (B_*S_)
#define QSCALE_ 0.18033688011112042f   // 0.125 * log2(e)

__device__ __half g_x [M_*E_];
__device__ __half g_wq[E_*E_];
__device__ __half g_wk[E_*E_];
__device__ __half g_wv[E_*E_];
__device__ __half g_wo[E_*E_];
__device__ __half g_q[B_*H_*S_*D_];
__device__ __half g_k[B_*H_*S_*D_];
__device__ __half g_v[B_*H_*S_*D_];
__device__ __half g_att[B_*S_*E_];

// ---------------------------------------------------------------------------
// helpers
// ---------------------------------------------------------------------------
__device__ __forceinline__ uint32_t packh2(float lo, float hi) {
    uint32_t r;
    asm("cvt.rn.f16x2.f32 %0, %1, %2;" : "=r"(r) : "f"(hi), "f"(lo));
    return r;
}

__device__ __forceinline__ uint32_t h2exp2(uint32_t x) {
    uint32_t r;
    asm("ex2.approx.f16x2 %0, %1;" : "=r"(r) : "r"(x));
    return r;
}

__device__ __forceinline__ void mma_f16(float c[4], const uint32_t a[4],
                                        uint32_t b0, uint32_t b1) {
    asm volatile(
        "mma.sync.aligned.m16n8k16.row.col.f32.f16.f16.f32 "
        "{%0,%1,%2,%3}, {%4,%5,%6,%7}, {%8,%9}, {%0,%1,%2,%3};"
        : "+f"(c[0]), "+f"(c[1]), "+f"(c[2]), "+f"(c[3])
        : "r"(a[0]), "r"(a[1]), "r"(a[2]), "r"(a[3]), "r"(b0), "r"(b1));
}

__device__ __forceinline__ void ldsm_x4(uint32_t& r0, uint32_t& r1,
                                        uint32_t& r2, uint32_t& r3,
                                        uint32_t addr) {
    asm volatile("ldmatrix.sync.aligned.m8n8.x4.shared.b16 {%0,%1,%2,%3}, [%4];"
                 : "=r"(r0), "=r"(r1), "=r"(r2), "=r"(r3) : "r"(addr));
}

__device__ __forceinline__ void ldsm_x4_t(uint32_t& r0, uint32_t& r1,
                                          uint32_t& r2, uint32_t& r3,
                                          uint32_t addr) {
    asm volatile("ldmatrix.sync.aligned.m8n8.x4.trans.shared.b16 {%0,%1,%2,%3}, [%4];"
                 : "=r"(r0), "=r"(r1), "=r"(r2), "=r"(r3) : "r"(addr));
}

__device__ __forceinline__ uint32_t s2u(const void* p) {
    uint32_t a;
    asm("{ .reg .u64 t; cvta.to.shared.u64 t, %1; cvt.u32.u64 %0, t; }"
        : "=r"(a) : "l"(p));
    return a;
}

__device__ __forceinline__ void cp16(uint32_t smem, const void* g) {
    asm volatile("cp.async.ca.shared.global [%0], [%1], 16;"
                 :: "r"(smem), "l"(g) : "memory");
}
#define CP_COMMIT() asm volatile("cp.async.commit_group;" ::: "memory")
#define CP_WAIT1()  asm volatile("cp.async.wait_group 1;" ::: "memory")
#define CP_WAIT0()  asm volatile("cp.async.wait_group 0;" ::: "memory")

// ---------------------------------------------------------------------------
// merged f32 -> f16 conversion
// ---------------------------------------------------------------------------
#define NX4 (M_ * E_ / 4)
#define NW4 (E_ * E_ / 4)
#define NTOT4 (NX4 + 4 * NW4)

__global__ void f2h_all_kernel(const float* __restrict__ x,
                               const float* __restrict__ wq,
                               const float* __restrict__ wk,
                               const float* __restrict__ wv,
                               const float* __restrict__ wo)
{
    int i = blockIdx.x * blockDim.x + threadIdx.x;
    if (i >= NTOT4) return;
    const float* src;
    __half* dst;
    int off;
    if (i < NX4) { src = x; dst = g_x; off = i; }
    else {
        int j = i - NX4;
        int sel = j / NW4;
        off = j - sel * NW4;
        src = (sel == 0) ? wq : (sel == 1) ? wk : (sel == 2) ? wv : wo;
        dst = (sel == 0) ? g_wq : (sel == 1) ? g_wk : (sel == 2) ? g_wv : g_wo;
    }
    float4 v = ((const float4*)src)[off];
    uint2 o;
    o.x = packh2(v.x, v.y);
    o.y = packh2(v.z, v.w);
    ((uint2*)dst)[off] = o;
}

// ---------------------------------------------------------------------------
// fp16 GEMM: BK=32 halves, 3-stage cp.async ring, one sync per k-tile.
// Block 128x128, 128 threads, 4 warps 2x2, warp tile 64x64.
// smem rows 20 words (16 data + 4 pad) -> ldmatrix conflict-free.
// 20.5KB/stage, 61.4KB total -> 3 CTAs/SM (12 warps).
// ---------------------------------------------------------------------------
#define GM 128
#define GN 128
#define GKH 32
#define GSTW 20
#define STAGE_W (GM * GSTW)                 // 2560 words per operand
#define NKT (E_ / GKH)                      // 32
#define GEMM_SMEM (3 * 2 * STAGE_W * 4)     // 61440 B

template<int MODE>
__global__ __launch_bounds__(128, 3)
void gemm_h_kernel(const __half* __restrict__ Ah,
                   const __half* __restrict__ Wq, const __half* __restrict__ Wk,
                   const __half* __restrict__ Wv,
                   __half* __restrict__ Cq, __half* __restrict__ Ck,
                   __half* __restrict__ Cv, float* __restrict__ Cf)
{
    extern __shared__ uint32_t dsm[];

    const __half* Wh = (MODE == 1) ? Wq
                     : (blockIdx.z == 0) ? Wq : (blockIdx.z == 1) ? Wk : Wv;
    __half* Ch = (blockIdx.z == 0) ? Cq : (blockIdx.z == 1) ? Ck : Cv;
    const float oscale = (MODE == 0 && blockIdx.z == 0) ? QSCALE_ : 1.0f;

    const int tid  = threadIdx.x;
    const int wid  = tid >> 5;
    const int lane = tid & 31;
    const int g    = lane >> 2;
    const int t    = lane & 3;
    const int wm   = (wid & 1) * 64;
    const int wn   = (wid >> 1) * 64;
    const int m0   = blockIdx.y * GM;
    const int n0   = blockIdx.x * GN;

    const uint32_t sbase = s2u(dsm);
    const uint32_t aoff = (((lane & 15) * GSTW) + ((lane >> 4) * 4)) * 4u;
    const uint32_t boff = ((((lane >> 4) * 8 + (lane & 7)) * GSTW)
                          + (((lane >> 3) & 1) * 4)) * 4u;

    const int crow = tid >> 2;     // 0..31
    const int cchk = tid & 3;      // 0..3 (16B chunks of 64B row)

    float acc[4][8][4];
    #pragma unroll
    for (int mi = 0; mi < 4; mi++)
        #pragma unroll
        for (int ni = 0; ni < 8; ni++)
            #pragma unroll
            for (int r = 0; r < 4; r++) acc[mi][ni][r] = 0.0f;

    auto issue = [&](int kt, int s) {
        const uint32_t sa = sbase + (uint32_t)(s * 2 * STAGE_W) * 4u;
        const uint32_t sw = sa + (uint32_t)STAGE_W * 4u;
        const __half* Agp = Ah + (size_t)(m0 + crow) * E_ + kt * GKH + cchk * 8;
        const __half* Wgp = Wh + (size_t)(n0 + crow) * E_ + kt * GKH + cchk * 8;
        #pragma unroll
        for (int i = 0; i < 4; i++) {
            const uint32_t so = (uint32_t)((crow + i * 32) * GSTW + cchk * 4) * 4u;
            cp16(sa + so, Agp + (size_t)(i * 32) * E_);
            cp16(sw + so, Wgp + (size_t)(i * 32) * E_);
        }
        CP_COMMIT();
    };

    issue(0, 0);
    issue(1, 1);

    for (int kt = 0; kt < NKT; kt++) {
        if (kt + 1 < NKT) { CP_WAIT1(); } else { CP_WAIT0(); }
        __syncthreads();
        if (kt + 2 < NKT) issue(kt + 2, (kt + 2) % 3);

        const int cs = kt % 3;
        const uint32_t bufA = sbase + (uint32_t)(cs * 2 * STAGE_W) * 4u;
        const uint32_t bufW = bufA + (uint32_t)STAGE_W * 4u;
        #pragma unroll
        for (int ks = 0; ks < 2; ks++) {
            const uint32_t kb = ks * 32u;          // 8 words = 16 halves
            uint32_t a[4][4];
            #pragma unroll
            for (int mi = 0; mi < 4; mi++)
                ldsm_x4(a[mi][0], a[mi][1], a[mi][2], a[mi][3],
                        bufA + aoff + (uint32_t)((wm + mi * 16) * GSTW) * 4u + kb);
            uint32_t b[8][2];
            #pragma unroll
            for (int pr = 0; pr < 4; pr++)
                ldsm_x4(b[2*pr][0], b[2*pr][1], b[2*pr+1][0], b[2*pr+1][1],
                        bufW + boff + (uint32_t)((wn + pr * 16) * GSTW) * 4u + kb);
            #pragma unroll
            for (int mi = 0; mi < 4; mi++)
                #pragma unroll
                for (int ni = 0; ni < 8; ni++)
                    mma_f16(acc[mi][ni], a[mi], b[ni][0], b[ni][1]);
        }
    }

    #pragma unroll
    for (int mi = 0; mi < 4; mi++) {
        #pragma unroll
        for (int ni = 0; ni < 8; ni++) {
            const int col = n0 + wn + ni * 8 + 2 * t;
            #pragma unroll
            for (int half = 0; half < 2; half++) {
                const int row = m0 + wm + mi * 16 + g + half * 8;
                if (MODE == 0) {
                    const int b = row >> 11;
                    const int s = row & (S_ - 1);
                    const int h = col >> 6;
                    const int d = col & (D_ - 1);
                    uint32_t hv = packh2(acc[mi][ni][half*2+0] * oscale,
                                         acc[mi][ni][half*2+1] * oscale);
                    *(uint32_t*)(Ch + ((size_t)(b * H_ + h) * S_ + s) * D_ + d) = hv;
                } else {
                    float2 v;
                    v.x = acc[mi][ni][half * 2 + 0];
                    v.y = acc[mi][ni][half * 2 + 1];
                    *(float2*)(Cf + (size_t)row * E_ + col) = v;
                }
            }
        }
    }
}

// ---------------------------------------------------------------------------
// fp16 flash attention (unchanged from R12 passing version).
// ---------------------------------------------------------------------------
#define AQT 128
#define AKT 64
#define AST 36
#define QW (AQT * AST)
#define KVW (AKT * AST)
#define STG_W (2 * KVW)
#define NT (S_ / AKT)
#define ATTN_SMEM ((QW + 3 * STG_W) * 4)
#define ONES2 0x3C003C00u

__global__ __launch_bounds__(256, 2)
void attn_f16_kernel()
{
    extern __shared__ uint32_t dsm[];

    const int tid  = threadIdx.x;
    const int w    = tid >> 5;
    const int lane = tid & 31;
    const int g    = lane >> 2;
    const int t    = lane & 3;
    const int bh   = blockIdx.y;
    const int q0   = blockIdx.x * AQT;
    const int qrow = q0 + w * 16;

    const uint32_t sbase = s2u(dsm);
    const uint32_t kvbase = sbase + (uint32_t)QW * 4u;
    const uint32_t aoffQ = (((w * 16 + (lane & 15)) * AST) + ((lane >> 4) * 4)) * 4u;
    const uint32_t boffK = ((((lane >> 4) * 8 + (lane & 7)) * AST)
                           + (((lane >> 3) & 1) * 4)) * 4u;
    const uint32_t voffV = (((lane & 15) * AST) + ((lane >> 4) * 4)) * 4u;

    const __half* Kb = g_k + (size_t)bh * S_ * D_;
    const __half* Vb = g_v + (size_t)bh * S_ * D_;
    const int crow = tid >> 3;
    const int cchk = tid & 7;

    auto issue = [&](int jt, int s) {
        const uint32_t sk = kvbase + (uint32_t)(s * STG_W) * 4u;
        const uint32_t sv = sk + (uint32_t)KVW * 4u;
        const __half* Kg = Kb + (size_t)(jt * AKT + crow) * D_ + cchk * 8;
        const __half* Vg = Vb + (size_t)(jt * AKT + crow) * D_ + cchk * 8;
        #pragma unroll
        for (int i = 0; i < 2; i++) {
            const uint32_t so = (uint32_t)((crow + i * 32) * AST + cchk * 4) * 4u;
            cp16(sk + so, Kg + (size_t)(i * 32) * D_);
            cp16(sv + so, Vg + (size_t)(i * 32) * D_);
        }
        CP_COMMIT();
    };

    {
        const uint4* Qg = (const uint4*)(g_q + ((size_t)bh * S_ + q0) * D_);
        #pragma unroll
        for (int i = 0; i < 4; i++) {
            const int idx = tid + i * 256;
            const int r = idx >> 3, c = idx & 7;
            *(uint4*)&dsm[r * AST + c * 4] = Qg[idx];
        }
    }
    issue(0, 0);
    issue(1, 1);
    __syncthreads();

    uint32_t aq[4][4];
    #pragma unroll
    for (int kc = 0; kc < 4; kc++)
        ldsm_x4(aq[kc][0], aq[kc][1], aq[kc][2], aq[kc][3],
                sbase + aoffQ + kc * 32u);

    float oacc[8][4];
    #pragma unroll
    for (int ni = 0; ni < 8; ni++)
        #pragma unroll
        for (int r = 0; r < 4; r++) oacc[ni][r] = 0.0f;
    float lacc[4] = {0.0f, 0.0f, 0.0f, 0.0f};

    float mA = -1e30f, mB = -1e30f;

    for (int jt = 0; jt < NT; jt++) {
        if (jt + 1 < NT) { CP_WAIT1(); } else { CP_WAIT0(); }
        __syncthreads();
        if (jt + 2 < NT) issue(jt + 2, (jt + 2) % 3);

        const int cs = jt % 3;
        const uint32_t baseK = kvbase + (uint32_t)(cs * STG_W) * 4u;
        const uint32_t baseV = baseK + (uint32_t)KVW * 4u;

        float sc[8][4];
        #pragma unroll
        for (int ni = 0; ni < 8; ni++)
            #pragma unroll
            for (int r = 0; r < 4; r++) sc[ni][r] = 0.0f;

        #pragma unroll
        for (int kc = 0; kc < 4; kc++) {
            const uint32_t kb = kc * 32u;
            #pragma unroll
            for (int pr = 0; pr < 4; pr++) {
                uint32_t b0, b1, b2, b3;
                ldsm_x4(b0, b1, b2, b3,
                        baseK + boffK + (uint32_t)(pr * 16 * AST) * 4u + kb);
                mma_f16(sc[2*pr],     aq[kc], b0, b1);
                mma_f16(sc[2*pr + 1], aq[kc], b2, b3);
            }
        }

        float rmA = -1e30f, rmB = -1e30f;
        #pragma unroll
        for (int ni = 0; ni < 8; ni++) {
            rmA = fmaxf(rmA, fmaxf(sc[ni][0], sc[ni][1]));
            rmB = fmaxf(rmB, fmaxf(sc[ni][2], sc[ni][3]));
        }
        rmA = fmaxf(rmA, __shfl_xor_sync(0xffffffffu, rmA, 1));
        rmA = fmaxf(rmA, __shfl_xor_sync(0xffffffffu, rmA, 2));
        rmB = fmaxf(rmB, __shfl_xor_sync(0xffffffffu, rmB, 1));
        rmB = fmaxf(rmB, __shfl_xor_sync(0xffffffffu, rmB, 2));

        const float nmA = fmaxf(mA, rmA);
        const float nmB = fmaxf(mB, rmB);
        const float cfA = exp2f(mA - nmA);
        const float cfB = exp2f(mB - nmB);
        mA = nmA; mB = nmB;

        lacc[0] *= cfA; lacc[1] *= cfA;
        lacc[2] *= cfB; lacc[3] *= cfB;
        #pragma unroll
        for (int ni = 0; ni < 8; ni++) {
            oacc[ni][0] *= cfA; oacc[ni][1] *= cfA;
            oacc[ni][2] *= cfB; oacc[ni][3] *= cfB;
        }

        #pragma unroll
        for (int kc = 0; kc < 4; kc++) {
            uint32_t ap[4];
            ap[0] = h2exp2(packh2(sc[2*kc][0]   - mA, sc[2*kc][1]   - mA));
            ap[1] = h2exp2(packh2(sc[2*kc][2]   - mB, sc[2*kc][3]   - mB));
            ap[2] = h2exp2(packh2(sc[2*kc+1][0] - mA, sc[2*kc+1][1] - mA));
            ap[3] = h2exp2(packh2(sc[2*kc+1][2] - mB, sc[2*kc+1][3] - mB));
            mma_f16(lacc, ap, ONES2, ONES2);
            const uint32_t krows = (uint32_t)(kc * 16 * AST) * 4u;
            #pragma unroll
            for (int npr = 0; npr < 4; npr++) {
                uint32_t b0, b1, b2, b3;
                ldsm_x4_t(b0, b1, b2, b3, baseV + voffV + krows + npr * 32u);
                mma_f16(oacc[2*npr],     ap, b0, b1);
                mma_f16(oacc[2*npr + 1], ap, b2, b3);
            }
        }
    }

    const float ivA = 1.0f / lacc[0];
    const float ivB = 1.0f / lacc[2];
    const int b = bh / H_;
    const int h = bh % H_;
    __half* OA = g_att + ((size_t)(b * S_ + qrow + g    ) * E_) + h * D_;
    __half* OB = g_att + ((size_t)(b * S_ + qrow + g + 8) * E_) + h * D_;
    #pragma unroll
    for (int ni = 0; ni < 8; ni++) {
        *(uint32_t*)(OA + ni * 8 + 2 * t) = packh2(oacc[ni][0] * ivA, oacc[ni][1] * ivA);
        *(uint32_t*)(OB + ni * 8 + 2 * t) = packh2(oacc[ni][2] * ivB, oacc[ni][3] * ivB);
    }
}

// ---------------------------------------------------------------------------
// Launch
// ---------------------------------------------------------------------------
extern "C" void kernel_launch(void* const* d_in, const int* in_sizes, int n_in,
                              void* d_out, int out_size)
{
    (void)in_sizes; (void)n_in; (void)out_size;
    const float* x  = (const float*)d_in[0];
    const float* wq = (const float*)d_in[1];
    const float* wk = (const float*)d_in[2];
    const float* wv = (const float*)d_in[3];
    const float* wo = (const float*)d_in[4];
    float* out = (float*)d_out;

    __half *px, *pwq, *pwk, *pwv, *pwo, *pq, *pk, *pv, *pa;
    cudaGetSymbolAddress((void**)&px,  g_x);
    cudaGetSymbolAddress((void**)&pwq, g_wq);
    cudaGetSymbolAddress((void**)&pwk, g_wk);
    cudaGetSymbolAddress((void**)&pwv, g_wv);
    cudaGetSymbolAddress((void**)&pwo, g_wo);
    cudaGetSymbolAddress((void**)&pq,  g_q);
    cudaGetSymbolAddress((void**)&pk,  g_k);
    cudaGetSymbolAddress((void**)&pv,  g_v);
    cudaGetSymbolAddress((void**)&pa,  g_att);

    f2h_all_kernel<<<(NTOT4 + 255) / 256, 256>>>(x, wq, wk, wv, wo);

    cudaFuncSetAttribute(gemm_h_kernel<0>,
                         cudaFuncAttributeMaxDynamicSharedMemorySize, GEMM_SMEM);
    cudaFuncSetAttribute(gemm_h_kernel<1>,
                         cudaFuncAttributeMaxDynamicSharedMemorySize, GEMM_SMEM);

    gemm_h_kernel<0><<<dim3(E_ / GN, M_ / GM, 3), 128, GEMM_SMEM>>>(
        px, pwq, pwk, pwv, pq, pk, pv, nullptr);

    cudaFuncSetAttribute(attn_f16_kernel,
                         cudaFuncAttributeMaxDynamicSharedMemorySize, ATTN_SMEM);
    attn_f16_kernel<<<dim3(S_ / AQT, B_ * H_), 256, ATTN_SMEM>>>();

    gemm_h_kernel<1><<<dim3(E_ / GN, M_ / GM, 1), 128, GEMM_SMEM>>>(
        pa, pwo, nullptr, nullptr, nullptr, nullptr, nullptr, out);
}